// round 6
// baseline (speedup 1.0000x reference)
#include <cuda_runtime.h>
#include <cuda_bf16.h>
#include <math.h>
#include <stdint.h>

// Problem constants
#define NN 30000       // node_size
#define RR 1000        // rel_size
#define TT 200000      // triple_size
#define DD 128         // DIM
#define BB 2048        // BATCH
#define OD 768         // output feature dim (6 * 128)
#define NJ 30080       // padded column count for dot matrix (235*128)
#define MR 4096        // stacked query rows (l 0..2047, r 2048..4095)
#define GAMMA_C 3.0f
#define LAMB_C 30.0f
#define TAU_C 10.0f
#define KCH 12         // 768 / 64 K-chunks in GEMM

// ---------------- scratch (device globals; no allocation allowed) ----------------
__device__ float g_tri[(size_t)TT * DD];
__device__ float g_att[4 * TT];              // exp(logit) per edge: [e0, e1, r0, r1]
__device__ float g_acc[(size_t)NN * DD];
__device__ float g_z[NN];
__device__ float g_feats[(size_t)NN * DD];
__device__ float g_out[(size_t)NN * OD];
__device__ float g_embsq[NN];
__device__ float g_A[(size_t)MR * OD];
__device__ float g_asq[MR];
__device__ float g_pos[BB];
__device__ float g_dot[(size_t)MR * NJ];
__device__ float g_mu[MR];
__device__ float g_sd[MR];
__device__ float g_mx[MR];
__device__ float g_lse[MR];
// bf16 split operands for tensor-core GEMM
__device__ __align__(16) __nv_bfloat16 g_Ahi[(size_t)MR * OD];
__device__ __align__(16) __nv_bfloat16 g_Alo[(size_t)MR * OD];
__device__ __align__(16) __nv_bfloat16 g_Bhi[(size_t)NJ * OD];
__device__ __align__(16) __nv_bfloat16 g_Blo[(size_t)NJ * OD];

// ---------------- helpers ----------------
__device__ __forceinline__ float warp_sum_f(float v) {
#pragma unroll
    for (int o = 16; o; o >>= 1) v += __shfl_xor_sync(0xffffffffu, v, o);
    return v;
}
__device__ __forceinline__ uint32_t smem_u32(const void* p) {
    uint32_t a;
    asm("{ .reg .u64 t; cvta.to.shared.u64 t, %1; cvt.u32.u64 %0, t; }" : "=r"(a) : "l"(p));
    return a;
}
__device__ __forceinline__ uint32_t swz128(uint32_t b) { return b ^ ((b >> 3) & 0x70); }

__device__ __forceinline__ void cp16(uint32_t dst, const void* src) {
    asm volatile("cp.async.cg.shared.global [%0], [%1], 16;" :: "r"(dst), "l"(src));
}
#define CP_COMMIT() asm volatile("cp.async.commit_group;" ::: "memory")
#define CP_WAIT(n)  asm volatile("cp.async.wait_group %0;" :: "n"(n) : "memory")

__device__ __forceinline__ void ldsm4(uint32_t* r, uint32_t addr) {
    asm volatile("ldmatrix.sync.aligned.m8n8.x4.shared.b16 {%0,%1,%2,%3}, [%4];"
                 : "=r"(r[0]), "=r"(r[1]), "=r"(r[2]), "=r"(r[3]) : "r"(addr));
}
__device__ __forceinline__ void mma_bf16(float* c, const uint32_t* a, uint32_t b0, uint32_t b1) {
    asm volatile(
        "mma.sync.aligned.m16n8k16.row.col.f32.bf16.bf16.f32 "
        "{%0,%1,%2,%3}, {%4,%5,%6,%7}, {%8,%9}, {%0,%1,%2,%3};"
        : "+f"(c[0]), "+f"(c[1]), "+f"(c[2]), "+f"(c[3])
        : "r"(a[0]), "r"(a[1]), "r"(a[2]), "r"(a[3]), "r"(b0), "r"(b1));
}

// ---------------- fill ----------------
__global__ void k_fill(int which) {
    size_t n = (which == 0) ? (size_t)NN * DD : (which == 1) ? (size_t)NN : (size_t)TT * DD;
    float* p = (which == 0) ? g_acc : (which == 1) ? g_z : g_tri;
    size_t i = (size_t)blockIdx.x * blockDim.x + threadIdx.x;
    if (i < n) p[i] = 0.0f;
}

// ---------------- tri_rel scatter ----------------
__global__ void k_tri_scatter(const int* __restrict__ r0, const int* __restrict__ r1,
                              const float* __restrict__ rval, const float* __restrict__ rel_emb) {
    int warp = (int)(((size_t)blockIdx.x * blockDim.x + threadIdx.x) >> 5);
    int lane = threadIdx.x & 31;
    if (warp >= TT) return;
    int seg = r0[warp];
    int rel = r1[warp];
    float v = rval[warp];
    float4 a = ((const float4*)(rel_emb + (size_t)rel * DD))[lane];
    float* dst = g_tri + (size_t)seg * DD + lane * 4;
    atomicAdd(dst + 0, v * a.x);
    atomicAdd(dst + 1, v * a.y);
    atomicAdd(dst + 2, v * a.z);
    atomicAdd(dst + 3, v * a.w);
}

// ---------------- normalize tri_rel + exp(attention logits) ----------------
__global__ void k_tri_norm(const float* __restrict__ attn_e, const float* __restrict__ attn_r) {
    int warp = (int)(((size_t)blockIdx.x * blockDim.x + threadIdx.x) >> 5);
    int lane = threadIdx.x & 31;
    if (warp >= TT) return;
    float4* p = (float4*)(g_tri + (size_t)warp * DD);
    float4 a = p[lane];
    float ss = a.x * a.x + a.y * a.y + a.z * a.z + a.w * a.w;
    ss = warp_sum_f(ss);
    float inv = 1.0f / fmaxf(sqrtf(ss), 1e-12f);
    a.x *= inv; a.y *= inv; a.z *= inv; a.w *= inv;
    p[lane] = a;

    float4 k0 = ((const float4*)attn_e)[lane];
    float4 k1 = ((const float4*)(attn_e + DD))[lane];
    float4 k2 = ((const float4*)attn_r)[lane];
    float4 k3 = ((const float4*)(attn_r + DD))[lane];
    float d0 = a.x * k0.x + a.y * k0.y + a.z * k0.z + a.w * k0.w;
    float d1 = a.x * k1.x + a.y * k1.y + a.z * k1.z + a.w * k1.w;
    float d2 = a.x * k2.x + a.y * k2.y + a.z * k2.z + a.w * k2.w;
    float d3 = a.x * k3.x + a.y * k3.y + a.z * k3.z + a.w * k3.w;
    d0 = warp_sum_f(d0);
    d1 = warp_sum_f(d1);
    d2 = warp_sum_f(d2);
    d3 = warp_sum_f(d3);
    if (lane == 0) {
        g_att[0 * TT + warp] = expf(d0);
        g_att[1 * TT + warp] = expf(d1);
        g_att[2 * TT + warp] = expf(d2);
        g_att[3 * TT + warp] = expf(d3);
    }
}

// ---------------- sparse_mean scatter ----------------
__global__ void k_scatter_mean(const int* __restrict__ adj, const float* __restrict__ emb) {
    int warp = (int)(((size_t)blockIdx.x * blockDim.x + threadIdx.x) >> 5);
    int lane = threadIdx.x & 31;
    if (warp >= TT) return;
    int row = adj[warp];
    int col = adj[TT + warp];
    float4 a = ((const float4*)(emb + (size_t)col * DD))[lane];
    float* dst = g_acc + (size_t)row * DD + lane * 4;
    atomicAdd(dst + 0, a.x);
    atomicAdd(dst + 1, a.y);
    atomicAdd(dst + 2, a.z);
    atomicAdd(dst + 3, a.w);
    if (lane == 0) atomicAdd(&g_z[row], 1.0f);
}

__global__ void k_finalize_mean(int colofs) {
    size_t idx = (size_t)blockIdx.x * blockDim.x + threadIdx.x;
    if (idx >= (size_t)NN * DD) return;
    int n = (int)(idx / DD);
    int d = (int)(idx % DD);
    float c = fmaxf(g_z[n], 1.0f);
    float f = tanhf(g_acc[idx] / c);
    g_feats[idx] = f;
    g_out[(size_t)n * OD + colofs + d] = f;
}

// ---------------- GAT softmax denominator (att already exp'd) ----------------
__global__ void k_zsum(const int* __restrict__ adj, int attofs) {
    int e = blockIdx.x * blockDim.x + threadIdx.x;
    if (e >= TT) return;
    atomicAdd(&g_z[adj[e]], g_att[attofs + e]);
}

// ---------------- GAT reflected-neighbor weighted scatter ----------------
__global__ void k_reflect(const int* __restrict__ adj, int attofs) {
    int warp = (int)(((size_t)blockIdx.x * blockDim.x + threadIdx.x) >> 5);
    int lane = threadIdx.x & 31;
    if (warp >= TT) return;
    int row = adj[warp];
    int col = adj[TT + warp];
    float w = g_att[attofs + warp] / g_z[row];
    float4 t = ((const float4*)(g_tri + (size_t)warp * DD))[lane];
    float4 nb = ((const float4*)(g_feats + (size_t)col * DD))[lane];
    float s = nb.x * t.x + nb.y * t.y + nb.z * t.z + nb.w * t.w;
    s = warp_sum_f(s);
    float c2 = 2.0f * s;
    float* dst = g_acc + (size_t)row * DD + lane * 4;
    atomicAdd(dst + 0, w * (nb.x - c2 * t.x));
    atomicAdd(dst + 1, w * (nb.y - c2 * t.y));
    atomicAdd(dst + 2, w * (nb.z - c2 * t.z));
    atomicAdd(dst + 3, w * (nb.w - c2 * t.w));
}

__global__ void k_finalize_tanh(int colofs) {
    size_t idx = (size_t)blockIdx.x * blockDim.x + threadIdx.x;
    if (idx >= (size_t)NN * DD) return;
    int n = (int)(idx / DD);
    int d = (int)(idx % DD);
    float f = tanhf(g_acc[idx]);
    g_feats[idx] = f;
    g_out[(size_t)n * OD + colofs + d] = f;
}

// ---------------- emb row squared norms ----------------
__global__ void k_embsq() {
    int warp = (int)(((size_t)blockIdx.x * blockDim.x + threadIdx.x) >> 5);
    int lane = threadIdx.x & 31;
    if (warp >= NN) return;
    const float4* p = (const float4*)(g_out + (size_t)warp * OD);
    float ss = 0.0f;
#pragma unroll
    for (int j = lane; j < OD / 4; j += 32) {
        float4 a = p[j];
        ss += a.x * a.x + a.y * a.y + a.z * a.z + a.w * a.w;
    }
    ss = warp_sum_f(ss);
    if (lane == 0) g_embsq[warp] = ss;
}

// ---------------- gather A + pos ----------------
__global__ void k_pairprep(const int* __restrict__ pairs) {
    int i = blockIdx.x;
    int li = pairs[2 * i];
    int ri = pairs[2 * i + 1];
    const float* L = g_out + (size_t)li * OD;
    const float* R = g_out + (size_t)ri * OD;
    float part = 0.0f;
    for (int c = threadIdx.x; c < OD; c += 256) {
        float a = L[c];
        float b = R[c];
        g_A[(size_t)i * OD + c] = a;
        g_A[(size_t)(i + BB) * OD + c] = b;
        float d = a - b;
        part += d * d;
    }
    __shared__ float sh[8];
    int lane = threadIdx.x & 31, wid = threadIdx.x >> 5;
    part = warp_sum_f(part);
    if (lane == 0) sh[wid] = part;
    __syncthreads();
    if (threadIdx.x == 0) {
        float s = 0.0f;
        for (int w = 0; w < 8; w++) s += sh[w];
        g_pos[i] = s;
        g_asq[i] = g_embsq[li];
        g_asq[i + BB] = g_embsq[ri];
    }
}

// ---------------- bf16 hi/lo split conversions ----------------
__global__ void k_cvtA() {
    size_t i = (size_t)blockIdx.x * blockDim.x + threadIdx.x;
    if (i >= (size_t)MR * OD) return;
    float x = g_A[i];
    __nv_bfloat16 h = __float2bfloat16(x);
    g_Ahi[i] = h;
    g_Alo[i] = __float2bfloat16(x - __bfloat162float(h));
}
__global__ void k_cvtB() {
    size_t i = (size_t)blockIdx.x * blockDim.x + threadIdx.x;
    if (i >= (size_t)NJ * OD) return;
    size_t row = i / OD;
    float x = (row < NN) ? g_out[i] : 0.0f;
    __nv_bfloat16 h = __float2bfloat16(x);
    g_Bhi[i] = h;
    g_Blo[i] = __float2bfloat16(x - __bfloat162float(h));
}

// ---------------- mma.sync bf16x3 GEMM: g_dot = A @ B^T ----------------
// CTA tile 128(M) x 128(N), K chunk = 64 bf16. SMEM per stage: Ahi/Alo/Bhi/Blo
// each 128x64 bf16 (= 128B rows, SW128 swizzle) = 4*16KB; 2 stages = 128KB.
// 8 warps in 2(m) x 4(n); warp tile 64x32; frags m16n8k16, bf16x3 compensation.
// NOTE: B is [n][k] row-major (same structure as A) -> plain ldmatrix for BOTH.
__global__ __launch_bounds__(256, 1) void k_gemm_tc() {
    extern __shared__ char smraw[];
    uint32_t sm0 = smem_u32(smraw);
    uint32_t smbase = (sm0 + 1023u) & ~1023u;

    const int tid = threadIdx.x;
    const int warp = tid >> 5;
    const int lane = tid & 31;
    const int bi = blockIdx.x;   // M tile (0..31)
    const int bj = blockIdx.y;   // N tile (0..234)

    const uint4* srcs[4];
    srcs[0] = (const uint4*)g_Ahi + (size_t)(bi * 128) * 96;
    srcs[1] = (const uint4*)g_Alo + (size_t)(bi * 128) * 96;
    srcs[2] = (const uint4*)g_Bhi + (size_t)(bj * 128) * 96;
    srcs[3] = (const uint4*)g_Blo + (size_t)(bj * 128) * 96;

    // --- async fill of one 64-wide K chunk into a stage ---
    const int frow = tid >> 3;       // 0..31
    const int fc = tid & 7;          // 16B chunk in 128B row
#define FILL_STAGE(kc, stage)                                                    \
    do {                                                                         \
        uint32_t st_ = smbase + (stage) * 65536u;                                \
        _Pragma("unroll")                                                        \
        for (int m_ = 0; m_ < 4; m_++) {                                         \
            const uint4* src_ = srcs[m_];                                        \
            uint32_t tb_ = st_ + m_ * 16384u;                                    \
            _Pragma("unroll")                                                    \
            for (int i_ = 0; i_ < 4; i_++) {                                     \
                int row_ = frow + i_ * 32;                                       \
                cp16(tb_ + swz128((uint32_t)(row_ * 128 + fc * 16)),             \
                     src_ + (size_t)row_ * 96 + (kc) * 8 + fc);                  \
            }                                                                    \
        }                                                                        \
        CP_COMMIT();                                                             \
    } while (0)

    // per-warp fragment geometry
    const int wm = warp >> 2;        // 0..1
    const int wn = warp & 3;         // 0..3
    uint32_t mrow[4], brow[2];
#pragma unroll
    for (int mi = 0; mi < 4; mi++)
        mrow[mi] = (uint32_t)((wm * 64 + mi * 16 + (lane & 15)) * 128);
#pragma unroll
    for (int g = 0; g < 2; g++)
        brow[g] = (uint32_t)((wn * 32 + g * 16 + (lane & 7) + ((lane >> 3) & 1) * 8) * 128);
    const uint32_t csel = (uint32_t)(((lane >> 4) & 1) * 16);  // byte offset of k8 half

    float acc[4][4][4];
#pragma unroll
    for (int mi = 0; mi < 4; mi++)
#pragma unroll
        for (int nj = 0; nj < 4; nj++)
#pragma unroll
            for (int q = 0; q < 4; q++) acc[mi][nj][q] = 0.0f;

    FILL_STAGE(0, 0);

    for (int k = 0; k < KCH; k++) {
        int s = k & 1;
        if (k + 1 < KCH) { FILL_STAGE(k + 1, s ^ 1); CP_WAIT(1); }
        else CP_WAIT(0);
        __syncthreads();

        uint32_t Ahb = smbase + s * 65536u;
        uint32_t Alb = Ahb + 16384u;
        uint32_t Bhb = Ahb + 32768u;
        uint32_t Blb = Ahb + 49152u;
#pragma unroll
        for (int ks = 0; ks < 4; ks++) {
            uint32_t col = (uint32_t)(ks * 32) + csel;
            uint32_t ahi[4][4], alo[4][4], bhi[2][4], blo[2][4];
#pragma unroll
            for (int mi = 0; mi < 4; mi++) {
                uint32_t so = swz128(mrow[mi] + col);
                ldsm4(ahi[mi], Ahb + so);
                ldsm4(alo[mi], Alb + so);
            }
#pragma unroll
            for (int g = 0; g < 2; g++) {
                uint32_t so = swz128(brow[g] + col);
                ldsm4(bhi[g], Bhb + so);
                ldsm4(blo[g], Blb + so);
            }
#pragma unroll
            for (int mi = 0; mi < 4; mi++) {
#pragma unroll
                for (int nj = 0; nj < 4; nj++) {
                    int g = nj >> 1, h = nj & 1;
                    mma_bf16(acc[mi][nj], ahi[mi], bhi[g][h], bhi[g][h + 2]);
                    mma_bf16(acc[mi][nj], ahi[mi], blo[g][h], blo[g][h + 2]);
                    mma_bf16(acc[mi][nj], alo[mi], bhi[g][h], bhi[g][h + 2]);
                }
            }
        }
        __syncthreads();
    }

    // epilogue: acc frag layout -> g_dot
    const int mrow0 = bi * 128 + wm * 64;
    const int ncol0 = bj * 128 + wn * 32;
    const int rofs = lane >> 2;
    const int cofs = (lane & 3) * 2;
#pragma unroll
    for (int mi = 0; mi < 4; mi++) {
#pragma unroll
        for (int nj = 0; nj < 4; nj++) {
            size_t r0 = (size_t)(mrow0 + mi * 16 + rofs);
            size_t c0 = (size_t)(ncol0 + nj * 8 + cofs);
            float2 v0 = make_float2(acc[mi][nj][0], acc[mi][nj][1]);
            float2 v1 = make_float2(acc[mi][nj][2], acc[mi][nj][3]);
            *(float2*)(g_dot + r0 * NJ + c0) = v0;
            *(float2*)(g_dot + (r0 + 8) * NJ + c0) = v1;
        }
    }
#undef FILL_STAGE
}

// ---------------- pass 1: per-row mean / std / max ----------------
__global__ void k_pass1(const int* __restrict__ pairs) {
    const int i = blockIdx.x;
    const int p = i & (BB - 1);
    const int li = pairs[2 * p];
    const int ri = pairs[2 * p + 1];
    const float posg = g_pos[p] + GAMMA_C;
    const float asq = g_asq[i];
    const float* drow = g_dot + (size_t)i * NJ;
    double s = 0.0, s2 = 0.0;
    float mx = -3.4e38f;
    for (int j = threadIdx.x; j < NN; j += 256) {
        float neg = asq + g_embsq[j] - 2.0f * drow[j];
        float lv = posg - neg;
        float fac = 1.0f - (float)(j == li) - (float)(j == ri);
        lv *= fac;
        s += lv;
        s2 += (double)lv * (double)lv;
        mx = fmaxf(mx, lv);
    }
    __shared__ double sh_s[8], sh_s2[8];
    __shared__ float sh_m[8];
    int lane = threadIdx.x & 31, wid = threadIdx.x >> 5;
#pragma unroll
    for (int o = 16; o; o >>= 1) {
        s += __shfl_xor_sync(0xffffffffu, s, o);
        s2 += __shfl_xor_sync(0xffffffffu, s2, o);
        mx = fmaxf(mx, __shfl_xor_sync(0xffffffffu, mx, o));
    }
    if (lane == 0) { sh_s[wid] = s; sh_s2[wid] = s2; sh_m[wid] = mx; }
    __syncthreads();
    if (threadIdx.x == 0) {
        double S = 0.0, S2 = 0.0;
        float M = -3.4e38f;
        for (int w = 0; w < 8; w++) { S += sh_s[w]; S2 += sh_s2[w]; M = fmaxf(M, sh_m[w]); }
        double mu = S / (double)NN;
        double var = S2 / (double)NN - mu * mu;
        if (var < 0.0) var = 0.0;
        g_mu[i] = (float)mu;
        g_sd[i] = (float)fmax(sqrt(var), 1e-30);
        g_mx[i] = M;
    }
}

// ---------------- pass 2: logsumexp ----------------
__global__ void k_pass2(const int* __restrict__ pairs) {
    const int i = blockIdx.x;
    const int p = i & (BB - 1);
    const int li = pairs[2 * p];
    const int ri = pairs[2 * p + 1];
    const float posg = g_pos[p] + GAMMA_C;
    const float asq = g_asq[i];
    const float mu = g_mu[i];
    const float sd = g_sd[i];
    const float mx = g_mx[i];
    const float sc = LAMB_C / sd;
    const float Mt = sc * (mx - mu);
    const float* drow = g_dot + (size_t)i * NJ;
    double se = 0.0;
    for (int j = threadIdx.x; j < NN; j += 256) {
        float neg = asq + g_embsq[j] - 2.0f * drow[j];
        float lv = posg - neg;
        float fac = 1.0f - (float)(j == li) - (float)(j == ri);
        lv *= fac;
        float t = sc * (lv - mu);
        se += (double)expf(t - Mt);
    }
    __shared__ double sh[8];
    int lane = threadIdx.x & 31, wid = threadIdx.x >> 5;
#pragma unroll
    for (int o = 16; o; o >>= 1) se += __shfl_xor_sync(0xffffffffu, se, o);
    if (lane == 0) sh[wid] = se;
    __syncthreads();
    if (threadIdx.x == 0) {
        double S = 0.0;
        for (int w = 0; w < 8; w++) S += sh[w];
        g_lse[i] = (float)((double)Mt + TAU_C + log(S));
    }
}

// ---------------- final mean ----------------
__global__ void k_final(float* __restrict__ out, int out_size) {
    double s = 0.0;
    for (int i = threadIdx.x; i < MR; i += 256) s += (double)g_lse[i];
    __shared__ double sh[8];
    int lane = threadIdx.x & 31, wid = threadIdx.x >> 5;
#pragma unroll
    for (int o = 16; o; o >>= 1) s += __shfl_xor_sync(0xffffffffu, s, o);
    if (lane == 0) sh[wid] = s;
    __syncthreads();
    if (threadIdx.x == 0) {
        double S = 0.0;
        for (int w = 0; w < 8; w++) S += sh[w];
        float val = (float)(S / (double)BB);
        for (int k = 0; k < out_size; k++) out[k] = val;
    }
}

// ---------------- host launch ----------------
extern "C" void kernel_launch(void* const* d_in, const int* in_sizes, int n_in,
                              void* d_out, int out_size) {
    const int* pairs = (const int*)d_in[0];
    const int* ent_adj = (const int*)d_in[1];
    const int* rel_adj = (const int*)d_in[2];
    const int* adj_list = (const int*)d_in[3];
    const int* r_index = (const int*)d_in[4];
    const float* r_val = (const float*)d_in[5];
    const float* ent_emb = (const float*)d_in[7];
    const float* rel_emb = (const float*)d_in[8];
    const float* attn_e = (const float*)d_in[9];
    const float* attn_r = (const float*)d_in[10];
    float* out = (float*)d_out;

    const int NT = 256;
    const int gb_tri = (int)(((size_t)TT * DD + NT - 1) / NT);
    const int gb_acc = (int)(((size_t)NN * DD + NT - 1) / NT);
    const int gb_z = (NN + NT - 1) / NT;
    const int gb_ew = (int)(((size_t)TT * 32 + NT - 1) / NT);
    const int gb_et = (TT + NT - 1) / NT;
    const int gb_nw = (int)(((size_t)NN * 32 + NT - 1) / NT);

    // tri_rel + attention exp-logits
    k_fill<<<gb_tri, NT>>>(2);
    k_tri_scatter<<<gb_ew, NT>>>(r_index, r_index + TT, r_val, rel_emb);
    k_tri_norm<<<gb_ew, NT>>>(attn_e, attn_r);

    // ---- GAT over ent_feature ----
    k_fill<<<gb_acc, NT>>>(0);
    k_fill<<<gb_z, NT>>>(1);
    k_scatter_mean<<<gb_ew, NT>>>(ent_adj, ent_emb);
    k_finalize_mean<<<gb_acc, NT>>>(0);
    for (int l = 0; l < 2; l++) {
        k_fill<<<gb_z, NT>>>(1);
        k_zsum<<<gb_et, NT>>>(adj_list, l * TT);
        k_fill<<<gb_acc, NT>>>(0);
        k_reflect<<<gb_ew, NT>>>(adj_list, l * TT);
        k_finalize_tanh<<<gb_acc, NT>>>((l + 1) * DD);
    }

    // ---- GAT over rel_feature ----
    k_fill<<<gb_acc, NT>>>(0);
    k_fill<<<gb_z, NT>>>(1);
    k_scatter_mean<<<gb_ew, NT>>>(rel_adj, rel_emb);
    k_finalize_mean<<<gb_acc, NT>>>(3 * DD);
    for (int l = 0; l < 2; l++) {
        k_fill<<<gb_z, NT>>>(1);
        k_zsum<<<gb_et, NT>>>(adj_list, (2 + l) * TT);
        k_fill<<<gb_acc, NT>>>(0);
        k_reflect<<<gb_ew, NT>>>(adj_list, (2 + l) * TT);
        k_finalize_tanh<<<gb_acc, NT>>>((4 + l) * DD);
    }

    // ---- align loss ----
    k_embsq<<<gb_nw, NT>>>();
    k_pairprep<<<BB, NT>>>(pairs);
    k_cvtA<<<(int)(((size_t)MR * OD + NT - 1) / NT), NT>>>();
    k_cvtB<<<(int)(((size_t)NJ * OD + NT - 1) / NT), NT>>>();

    const int gemm_smem = 2 * 65536 + 1024;  // 2 stages + alignment pad
    cudaFuncSetAttribute(k_gemm_tc, cudaFuncAttributeMaxDynamicSharedMemorySize, gemm_smem);
    dim3 gg(MR / 128, NJ / 128);  // (32, 235): wave covers all M tiles -> B reuse in L2
    k_gemm_tc<<<gg, 256, gemm_smem>>>();

    k_pass1<<<MR, 256>>>(pairs);
    k_pass2<<<MR, 256>>>(pairs);
    k_final<<<1, 256>>>(out, out_size);
}

// round 7
// speedup vs baseline: 1.0001x; 1.0001x over previous
#include <cuda_runtime.h>
#include <cuda_bf16.h>
#include <math.h>
#include <stdint.h>

// Problem constants
#define NN 30000       // node_size
#define RR 1000        // rel_size
#define TT 200000      // triple_size
#define DD 128         // DIM
#define BB 2048        // BATCH
#define OD 768         // output feature dim (6 * 128)
#define NJ 30080       // padded column count for dot matrix (235*128)
#define MR 4096        // stacked query rows (l 0..2047, r 2048..4095)
#define GAMMA_C 3.0f
#define LAMB_C 30.0f
#define TAU_C 10.0f
#define KCH 12         // 768 / 64 K-chunks in GEMM

// ---------------- scratch (device globals; no allocation allowed) ----------------
__device__ float g_tri[(size_t)TT * DD];
__device__ float g_att[4 * TT];              // exp(logit) per edge: [e0, e1, r0, r1]
__device__ float g_acc[(size_t)NN * DD];
__device__ float g_z[NN];
__device__ float g_feats[(size_t)NN * DD];
__device__ float g_out[(size_t)NN * OD];
__device__ float g_embsq[NN];
__device__ float g_A[(size_t)MR * OD];
__device__ float g_asq[MR];
__device__ float g_pos[BB];
__device__ float g_dot[(size_t)MR * NJ];
__device__ float g_mu[MR];
__device__ float g_sd[MR];
__device__ float g_mx[MR];
__device__ float g_lse[MR];
// bf16 split operands for tensor-core GEMM
__device__ __align__(16) __nv_bfloat16 g_Ahi[(size_t)MR * OD];
__device__ __align__(16) __nv_bfloat16 g_Alo[(size_t)MR * OD];
__device__ __align__(16) __nv_bfloat16 g_Bhi[(size_t)NJ * OD];
__device__ __align__(16) __nv_bfloat16 g_Blo[(size_t)NJ * OD];

// ---------------- helpers ----------------
__device__ __forceinline__ float warp_sum_f(float v) {
#pragma unroll
    for (int o = 16; o; o >>= 1) v += __shfl_xor_sync(0xffffffffu, v, o);
    return v;
}
__device__ __forceinline__ uint32_t smem_u32(const void* p) {
    uint32_t a;
    asm("{ .reg .u64 t; cvta.to.shared.u64 t, %1; cvt.u32.u64 %0, t; }" : "=r"(a) : "l"(p));
    return a;
}
__device__ __forceinline__ uint32_t swz128(uint32_t b) { return b ^ ((b >> 3) & 0x70); }

__device__ __forceinline__ void cp16(uint32_t dst, const void* src) {
    asm volatile("cp.async.cg.shared.global [%0], [%1], 16;" :: "r"(dst), "l"(src));
}
#define CP_COMMIT() asm volatile("cp.async.commit_group;" ::: "memory")
#define CP_WAIT(n)  asm volatile("cp.async.wait_group %0;" :: "n"(n) : "memory")

__device__ __forceinline__ void ldsm4(uint32_t* r, uint32_t addr) {
    asm volatile("ldmatrix.sync.aligned.m8n8.x4.shared.b16 {%0,%1,%2,%3}, [%4];"
                 : "=r"(r[0]), "=r"(r[1]), "=r"(r[2]), "=r"(r[3]) : "r"(addr));
}
__device__ __forceinline__ void mma_bf16(float* c, const uint32_t* a, uint32_t b0, uint32_t b1) {
    asm volatile(
        "mma.sync.aligned.m16n8k16.row.col.f32.bf16.bf16.f32 "
        "{%0,%1,%2,%3}, {%4,%5,%6,%7}, {%8,%9}, {%0,%1,%2,%3};"
        : "+f"(c[0]), "+f"(c[1]), "+f"(c[2]), "+f"(c[3])
        : "r"(a[0]), "r"(a[1]), "r"(a[2]), "r"(a[3]), "r"(b0), "r"(b1));
}

// ---------------- fill ----------------
__global__ void k_fill(int which) {
    size_t n = (which == 0) ? (size_t)NN * DD : (which == 1) ? (size_t)NN : (size_t)TT * DD;
    float* p = (which == 0) ? g_acc : (which == 1) ? g_z : g_tri;
    size_t i = (size_t)blockIdx.x * blockDim.x + threadIdx.x;
    if (i < n) p[i] = 0.0f;
}

// ---------------- tri_rel scatter ----------------
__global__ void k_tri_scatter(const int* __restrict__ r0, const int* __restrict__ r1,
                              const float* __restrict__ rval, const float* __restrict__ rel_emb) {
    int warp = (int)(((size_t)blockIdx.x * blockDim.x + threadIdx.x) >> 5);
    int lane = threadIdx.x & 31;
    if (warp >= TT) return;
    int seg = r0[warp];
    int rel = r1[warp];
    float v = rval[warp];
    float4 a = ((const float4*)(rel_emb + (size_t)rel * DD))[lane];
    float* dst = g_tri + (size_t)seg * DD + lane * 4;
    atomicAdd(dst + 0, v * a.x);
    atomicAdd(dst + 1, v * a.y);
    atomicAdd(dst + 2, v * a.z);
    atomicAdd(dst + 3, v * a.w);
}

// ---------------- normalize tri_rel + exp(attention logits) ----------------
__global__ void k_tri_norm(const float* __restrict__ attn_e, const float* __restrict__ attn_r) {
    int warp = (int)(((size_t)blockIdx.x * blockDim.x + threadIdx.x) >> 5);
    int lane = threadIdx.x & 31;
    if (warp >= TT) return;
    float4* p = (float4*)(g_tri + (size_t)warp * DD);
    float4 a = p[lane];
    float ss = a.x * a.x + a.y * a.y + a.z * a.z + a.w * a.w;
    ss = warp_sum_f(ss);
    float inv = 1.0f / fmaxf(sqrtf(ss), 1e-12f);
    a.x *= inv; a.y *= inv; a.z *= inv; a.w *= inv;
    p[lane] = a;

    float4 k0 = ((const float4*)attn_e)[lane];
    float4 k1 = ((const float4*)(attn_e + DD))[lane];
    float4 k2 = ((const float4*)attn_r)[lane];
    float4 k3 = ((const float4*)(attn_r + DD))[lane];
    float d0 = a.x * k0.x + a.y * k0.y + a.z * k0.z + a.w * k0.w;
    float d1 = a.x * k1.x + a.y * k1.y + a.z * k1.z + a.w * k1.w;
    float d2 = a.x * k2.x + a.y * k2.y + a.z * k2.z + a.w * k2.w;
    float d3 = a.x * k3.x + a.y * k3.y + a.z * k3.z + a.w * k3.w;
    d0 = warp_sum_f(d0);
    d1 = warp_sum_f(d1);
    d2 = warp_sum_f(d2);
    d3 = warp_sum_f(d3);
    if (lane == 0) {
        g_att[0 * TT + warp] = expf(d0);
        g_att[1 * TT + warp] = expf(d1);
        g_att[2 * TT + warp] = expf(d2);
        g_att[3 * TT + warp] = expf(d3);
    }
}

// ---------------- sparse_mean scatter ----------------
__global__ void k_scatter_mean(const int* __restrict__ adj, const float* __restrict__ emb) {
    int warp = (int)(((size_t)blockIdx.x * blockDim.x + threadIdx.x) >> 5);
    int lane = threadIdx.x & 31;
    if (warp >= TT) return;
    int row = adj[warp];
    int col = adj[TT + warp];
    float4 a = ((const float4*)(emb + (size_t)col * DD))[lane];
    float* dst = g_acc + (size_t)row * DD + lane * 4;
    atomicAdd(dst + 0, a.x);
    atomicAdd(dst + 1, a.y);
    atomicAdd(dst + 2, a.z);
    atomicAdd(dst + 3, a.w);
    if (lane == 0) atomicAdd(&g_z[row], 1.0f);
}

__global__ void k_finalize_mean(int colofs) {
    size_t idx = (size_t)blockIdx.x * blockDim.x + threadIdx.x;
    if (idx >= (size_t)NN * DD) return;
    int n = (int)(idx / DD);
    int d = (int)(idx % DD);
    float c = fmaxf(g_z[n], 1.0f);
    float f = tanhf(g_acc[idx] / c);
    g_feats[idx] = f;
    g_out[(size_t)n * OD + colofs + d] = f;
}

// ---------------- GAT softmax denominator (att already exp'd) ----------------
__global__ void k_zsum(const int* __restrict__ adj, int attofs) {
    int e = blockIdx.x * blockDim.x + threadIdx.x;
    if (e >= TT) return;
    atomicAdd(&g_z[adj[e]], g_att[attofs + e]);
}

// ---------------- GAT reflected-neighbor weighted scatter ----------------
__global__ void k_reflect(const int* __restrict__ adj, int attofs) {
    int warp = (int)(((size_t)blockIdx.x * blockDim.x + threadIdx.x) >> 5);
    int lane = threadIdx.x & 31;
    if (warp >= TT) return;
    int row = adj[warp];
    int col = adj[TT + warp];
    float w = g_att[attofs + warp] / g_z[row];
    float4 t = ((const float4*)(g_tri + (size_t)warp * DD))[lane];
    float4 nb = ((const float4*)(g_feats + (size_t)col * DD))[lane];
    float s = nb.x * t.x + nb.y * t.y + nb.z * t.z + nb.w * t.w;
    s = warp_sum_f(s);
    float c2 = 2.0f * s;
    float* dst = g_acc + (size_t)row * DD + lane * 4;
    atomicAdd(dst + 0, w * (nb.x - c2 * t.x));
    atomicAdd(dst + 1, w * (nb.y - c2 * t.y));
    atomicAdd(dst + 2, w * (nb.z - c2 * t.z));
    atomicAdd(dst + 3, w * (nb.w - c2 * t.w));
}

__global__ void k_finalize_tanh(int colofs) {
    size_t idx = (size_t)blockIdx.x * blockDim.x + threadIdx.x;
    if (idx >= (size_t)NN * DD) return;
    int n = (int)(idx / DD);
    int d = (int)(idx % DD);
    float f = tanhf(g_acc[idx]);
    g_feats[idx] = f;
    g_out[(size_t)n * OD + colofs + d] = f;
}

// ---------------- emb row squared norms ----------------
__global__ void k_embsq() {
    int warp = (int)(((size_t)blockIdx.x * blockDim.x + threadIdx.x) >> 5);
    int lane = threadIdx.x & 31;
    if (warp >= NN) return;
    const float4* p = (const float4*)(g_out + (size_t)warp * OD);
    float ss = 0.0f;
#pragma unroll
    for (int j = lane; j < OD / 4; j += 32) {
        float4 a = p[j];
        ss += a.x * a.x + a.y * a.y + a.z * a.z + a.w * a.w;
    }
    ss = warp_sum_f(ss);
    if (lane == 0) g_embsq[warp] = ss;
}

// ---------------- gather A + pos ----------------
__global__ void k_pairprep(const int* __restrict__ pairs) {
    int i = blockIdx.x;
    int li = pairs[2 * i];
    int ri = pairs[2 * i + 1];
    const float* L = g_out + (size_t)li * OD;
    const float* R = g_out + (size_t)ri * OD;
    float part = 0.0f;
    for (int c = threadIdx.x; c < OD; c += 256) {
        float a = L[c];
        float b = R[c];
        g_A[(size_t)i * OD + c] = a;
        g_A[(size_t)(i + BB) * OD + c] = b;
        float d = a - b;
        part += d * d;
    }
    __shared__ float sh[8];
    int lane = threadIdx.x & 31, wid = threadIdx.x >> 5;
    part = warp_sum_f(part);
    if (lane == 0) sh[wid] = part;
    __syncthreads();
    if (threadIdx.x == 0) {
        float s = 0.0f;
        for (int w = 0; w < 8; w++) s += sh[w];
        g_pos[i] = s;
        g_asq[i] = g_embsq[li];
        g_asq[i + BB] = g_embsq[ri];
    }
}

// ---------------- bf16 hi/lo split conversions ----------------
__global__ void k_cvtA() {
    size_t i = (size_t)blockIdx.x * blockDim.x + threadIdx.x;
    if (i >= (size_t)MR * OD) return;
    float x = g_A[i];
    __nv_bfloat16 h = __float2bfloat16(x);
    g_Ahi[i] = h;
    g_Alo[i] = __float2bfloat16(x - __bfloat162float(h));
}
__global__ void k_cvtB() {
    size_t i = (size_t)blockIdx.x * blockDim.x + threadIdx.x;
    if (i >= (size_t)NJ * OD) return;
    size_t row = i / OD;
    float x = (row < NN) ? g_out[i] : 0.0f;
    __nv_bfloat16 h = __float2bfloat16(x);
    g_Bhi[i] = h;
    g_Blo[i] = __float2bfloat16(x - __bfloat162float(h));
}

// ---------------- mma.sync bf16x3 GEMM: g_dot = A @ B^T ----------------
// CTA tile 128(M) x 128(N), K chunk = 64 bf16. SMEM per stage: Ahi/Alo/Bhi/Blo
// each 128x64 bf16 (= 128B rows, SW128 swizzle) = 4*16KB; 2 stages = 128KB.
// 8 warps in 2(m) x 4(n); warp tile 64x32; frags m16n8k16, bf16x3 compensation.
// NOTE: B is [n][k] row-major (same structure as A) -> plain ldmatrix for BOTH.
__global__ __launch_bounds__(256, 1) void k_gemm_tc() {
    extern __shared__ char smraw[];
    uint32_t sm0 = smem_u32(smraw);
    uint32_t smbase = (sm0 + 1023u) & ~1023u;

    const int tid = threadIdx.x;
    const int warp = tid >> 5;
    const int lane = tid & 31;
    const int bi = blockIdx.x;   // M tile (0..31)
    const int bj = blockIdx.y;   // N tile (0..234)

    const uint4* srcs[4];
    srcs[0] = (const uint4*)g_Ahi + (size_t)(bi * 128) * 96;
    srcs[1] = (const uint4*)g_Alo + (size_t)(bi * 128) * 96;
    srcs[2] = (const uint4*)g_Bhi + (size_t)(bj * 128) * 96;
    srcs[3] = (const uint4*)g_Blo + (size_t)(bj * 128) * 96;

    // --- async fill of one 64-wide K chunk into a stage ---
    const int frow = tid >> 3;       // 0..31
    const int fc = tid & 7;          // 16B chunk in 128B row
#define FILL_STAGE(kc, stage)                                                    \
    do {                                                                         \
        uint32_t st_ = smbase + (stage) * 65536u;                                \
        _Pragma("unroll")                                                        \
        for (int m_ = 0; m_ < 4; m_++) {                                         \
            const uint4* src_ = srcs[m_];                                        \
            uint32_t tb_ = st_ + m_ * 16384u;                                    \
            _Pragma("unroll")                                                    \
            for (int i_ = 0; i_ < 4; i_++) {                                     \
                int row_ = frow + i_ * 32;                                       \
                cp16(tb_ + swz128((uint32_t)(row_ * 128 + fc * 16)),             \
                     src_ + (size_t)row_ * 96 + (kc) * 8 + fc);                  \
            }                                                                    \
        }                                                                        \
        CP_COMMIT();                                                             \
    } while (0)

    // per-warp fragment geometry
    const int wm = warp >> 2;        // 0..1
    const int wn = warp & 3;         // 0..3
    uint32_t mrow[4], brow[2];
#pragma unroll
    for (int mi = 0; mi < 4; mi++)
        mrow[mi] = (uint32_t)((wm * 64 + mi * 16 + (lane & 15)) * 128);
#pragma unroll
    for (int g = 0; g < 2; g++)
        brow[g] = (uint32_t)((wn * 32 + g * 16 + (lane & 7) + ((lane >> 3) & 1) * 8) * 128);
    const uint32_t csel = (uint32_t)(((lane >> 4) & 1) * 16);  // byte offset of k8 half

    float acc[4][4][4];
#pragma unroll
    for (int mi = 0; mi < 4; mi++)
#pragma unroll
        for (int nj = 0; nj < 4; nj++)
#pragma unroll
            for (int q = 0; q < 4; q++) acc[mi][nj][q] = 0.0f;

    FILL_STAGE(0, 0);

    for (int k = 0; k < KCH; k++) {
        int s = k & 1;
        if (k + 1 < KCH) { FILL_STAGE(k + 1, s ^ 1); CP_WAIT(1); }
        else CP_WAIT(0);
        __syncthreads();

        uint32_t Ahb = smbase + s * 65536u;
        uint32_t Alb = Ahb + 16384u;
        uint32_t Bhb = Ahb + 32768u;
        uint32_t Blb = Ahb + 49152u;
#pragma unroll
        for (int ks = 0; ks < 4; ks++) {
            uint32_t col = (uint32_t)(ks * 32) + csel;
            uint32_t ahi[4][4], alo[4][4], bhi[2][4], blo[2][4];
#pragma unroll
            for (int mi = 0; mi < 4; mi++) {
                uint32_t so = swz128(mrow[mi] + col);
                ldsm4(ahi[mi], Ahb + so);
                ldsm4(alo[mi], Alb + so);
            }
#pragma unroll
            for (int g = 0; g < 2; g++) {
                uint32_t so = swz128(brow[g] + col);
                ldsm4(bhi[g], Bhb + so);
                ldsm4(blo[g], Blb + so);
            }
#pragma unroll
            for (int mi = 0; mi < 4; mi++) {
#pragma unroll
                for (int nj = 0; nj < 4; nj++) {
                    int g = nj >> 1, h = nj & 1;
                    mma_bf16(acc[mi][nj], ahi[mi], bhi[g][h], bhi[g][h + 2]);
                    mma_bf16(acc[mi][nj], ahi[mi], blo[g][h], blo[g][h + 2]);
                    mma_bf16(acc[mi][nj], alo[mi], bhi[g][h], bhi[g][h + 2]);
                }
            }
        }
        __syncthreads();
    }

    // epilogue: acc frag layout -> g_dot
    const int mrow0 = bi * 128 + wm * 64;
    const int ncol0 = bj * 128 + wn * 32;
    const int rofs = lane >> 2;
    const int cofs = (lane & 3) * 2;
#pragma unroll
    for (int mi = 0; mi < 4; mi++) {
#pragma unroll
        for (int nj = 0; nj < 4; nj++) {
            size_t r0 = (size_t)(mrow0 + mi * 16 + rofs);
            size_t c0 = (size_t)(ncol0 + nj * 8 + cofs);
            float2 v0 = make_float2(acc[mi][nj][0], acc[mi][nj][1]);
            float2 v1 = make_float2(acc[mi][nj][2], acc[mi][nj][3]);
            *(float2*)(g_dot + r0 * NJ + c0) = v0;
            *(float2*)(g_dot + (r0 + 8) * NJ + c0) = v1;
        }
    }
#undef FILL_STAGE
}

// ---------------- pass 1: per-row mean / std / max ----------------
__global__ void k_pass1(const int* __restrict__ pairs) {
    const int i = blockIdx.x;
    const int p = i & (BB - 1);
    const int li = pairs[2 * p];
    const int ri = pairs[2 * p + 1];
    const float posg = g_pos[p] + GAMMA_C;
    const float asq = g_asq[i];
    const float* drow = g_dot + (size_t)i * NJ;
    double s = 0.0, s2 = 0.0;
    float mx = -3.4e38f;
    for (int j = threadIdx.x; j < NN; j += 256) {
        float neg = asq + g_embsq[j] - 2.0f * drow[j];
        float lv = posg - neg;
        float fac = 1.0f - (float)(j == li) - (float)(j == ri);
        lv *= fac;
        s += lv;
        s2 += (double)lv * (double)lv;
        mx = fmaxf(mx, lv);
    }
    __shared__ double sh_s[8], sh_s2[8];
    __shared__ float sh_m[8];
    int lane = threadIdx.x & 31, wid = threadIdx.x >> 5;
#pragma unroll
    for (int o = 16; o; o >>= 1) {
        s += __shfl_xor_sync(0xffffffffu, s, o);
        s2 += __shfl_xor_sync(0xffffffffu, s2, o);
        mx = fmaxf(mx, __shfl_xor_sync(0xffffffffu, mx, o));
    }
    if (lane == 0) { sh_s[wid] = s; sh_s2[wid] = s2; sh_m[wid] = mx; }
    __syncthreads();
    if (threadIdx.x == 0) {
        double S = 0.0, S2 = 0.0;
        float M = -3.4e38f;
        for (int w = 0; w < 8; w++) { S += sh_s[w]; S2 += sh_s2[w]; M = fmaxf(M, sh_m[w]); }
        double mu = S / (double)NN;
        double var = S2 / (double)NN - mu * mu;
        if (var < 0.0) var = 0.0;
        g_mu[i] = (float)mu;
        g_sd[i] = (float)fmax(sqrt(var), 1e-30);
        g_mx[i] = M;
    }
}

// ---------------- pass 2: logsumexp ----------------
__global__ void k_pass2(const int* __restrict__ pairs) {
    const int i = blockIdx.x;
    const int p = i & (BB - 1);
    const int li = pairs[2 * p];
    const int ri = pairs[2 * p + 1];
    const float posg = g_pos[p] + GAMMA_C;
    const float asq = g_asq[i];
    const float mu = g_mu[i];
    const float sd = g_sd[i];
    const float mx = g_mx[i];
    const float sc = LAMB_C / sd;
    const float Mt = sc * (mx - mu);
    const float* drow = g_dot + (size_t)i * NJ;
    double se = 0.0;
    for (int j = threadIdx.x; j < NN; j += 256) {
        float neg = asq + g_embsq[j] - 2.0f * drow[j];
        float lv = posg - neg;
        float fac = 1.0f - (float)(j == li) - (float)(j == ri);
        lv *= fac;
        float t = sc * (lv - mu);
        se += (double)expf(t - Mt);
    }
    __shared__ double sh[8];
    int lane = threadIdx.x & 31, wid = threadIdx.x >> 5;
#pragma unroll
    for (int o = 16; o; o >>= 1) se += __shfl_xor_sync(0xffffffffu, se, o);
    if (lane == 0) sh[wid] = se;
    __syncthreads();
    if (threadIdx.x == 0) {
        double S = 0.0;
        for (int w = 0; w < 8; w++) S += sh[w];
        g_lse[i] = (float)((double)Mt + TAU_C + log(S));
    }
}

// ---------------- final mean ----------------
__global__ void k_final(float* __restrict__ out, int out_size) {
    double s = 0.0;
    for (int i = threadIdx.x; i < MR; i += 256) s += (double)g_lse[i];
    __shared__ double sh[8];
    int lane = threadIdx.x & 31, wid = threadIdx.x >> 5;
#pragma unroll
    for (int o = 16; o; o >>= 1) s += __shfl_xor_sync(0xffffffffu, s, o);
    if (lane == 0) sh[wid] = s;
    __syncthreads();
    if (threadIdx.x == 0) {
        double S = 0.0;
        for (int w = 0; w < 8; w++) S += sh[w];
        float val = (float)(S / (double)BB);
        for (int k = 0; k < out_size; k++) out[k] = val;
    }
}

// ---------------- host launch ----------------
extern "C" void kernel_launch(void* const* d_in, const int* in_sizes, int n_in,
                              void* d_out, int out_size) {
    const int* pairs = (const int*)d_in[0];
    const int* ent_adj = (const int*)d_in[1];
    const int* rel_adj = (const int*)d_in[2];
    const int* adj_list = (const int*)d_in[3];
    const int* r_index = (const int*)d_in[4];
    const float* r_val = (const float*)d_in[5];
    const float* ent_emb = (const float*)d_in[7];
    const float* rel_emb = (const float*)d_in[8];
    const float* attn_e = (const float*)d_in[9];
    const float* attn_r = (const float*)d_in[10];
    float* out = (float*)d_out;

    const int NT = 256;
    const int gb_tri = (int)(((size_t)TT * DD + NT - 1) / NT);
    const int gb_acc = (int)(((size_t)NN * DD + NT - 1) / NT);
    const int gb_z = (NN + NT - 1) / NT;
    const int gb_ew = (int)(((size_t)TT * 32 + NT - 1) / NT);
    const int gb_et = (TT + NT - 1) / NT;
    const int gb_nw = (int)(((size_t)NN * 32 + NT - 1) / NT);

    // tri_rel + attention exp-logits
    k_fill<<<gb_tri, NT>>>(2);
    k_tri_scatter<<<gb_ew, NT>>>(r_index, r_index + TT, r_val, rel_emb);
    k_tri_norm<<<gb_ew, NT>>>(attn_e, attn_r);

    // ---- GAT over ent_feature ----
    k_fill<<<gb_acc, NT>>>(0);
    k_fill<<<gb_z, NT>>>(1);
    k_scatter_mean<<<gb_ew, NT>>>(ent_adj, ent_emb);
    k_finalize_mean<<<gb_acc, NT>>>(0);
    for (int l = 0; l < 2; l++) {
        k_fill<<<gb_z, NT>>>(1);
        k_zsum<<<gb_et, NT>>>(adj_list, l * TT);
        k_fill<<<gb_acc, NT>>>(0);
        k_reflect<<<gb_ew, NT>>>(adj_list, l * TT);
        k_finalize_tanh<<<gb_acc, NT>>>((l + 1) * DD);
    }

    // ---- GAT over rel_feature ----
    k_fill<<<gb_acc, NT>>>(0);
    k_fill<<<gb_z, NT>>>(1);
    k_scatter_mean<<<gb_ew, NT>>>(rel_adj, rel_emb);
    k_finalize_mean<<<gb_acc, NT>>>(3 * DD);
    for (int l = 0; l < 2; l++) {
        k_fill<<<gb_z, NT>>>(1);
        k_zsum<<<gb_et, NT>>>(adj_list, (2 + l) * TT);
        k_fill<<<gb_acc, NT>>>(0);
        k_reflect<<<gb_ew, NT>>>(adj_list, (2 + l) * TT);
        k_finalize_tanh<<<gb_acc, NT>>>((4 + l) * DD);
    }

    // ---- align loss ----
    k_embsq<<<gb_nw, NT>>>();
    k_pairprep<<<BB, NT>>>(pairs);
    k_cvtA<<<(int)(((size_t)MR * OD + NT - 1) / NT), NT>>>();
    k_cvtB<<<(int)(((size_t)NJ * OD + NT - 1) / NT), NT>>>();

    const int gemm_smem = 2 * 65536 + 1024;  // 2 stages + alignment pad
    cudaFuncSetAttribute(k_gemm_tc, cudaFuncAttributeMaxDynamicSharedMemorySize, gemm_smem);
    dim3 gg(MR / 128, NJ / 128);  // (32, 235): wave covers all M tiles -> B reuse in L2
    k_gemm_tc<<<gg, 256, gemm_smem>>>();

    k_pass1<<<MR, 256>>>(pairs);
    k_pass2<<<MR, 256>>>(pairs);
    k_final<<<1, 256>>>(out, out_size);
}

// round 8
// speedup vs baseline: 1.0222x; 1.0221x over previous
#include <cuda_runtime.h>
#include <cuda_bf16.h>
#include <math.h>
#include <stdint.h>

// Problem constants
#define NN 30000       // node_size
#define RR 1000        // rel_size
#define TT 200000      // triple_size
#define DD 128         // DIM
#define BB 2048        // BATCH
#define OD 768         // output feature dim (6 * 128)
#define NJ 30080       // padded column count for dot matrix (235*128)
#define MR 4096        // stacked query rows (l 0..2047, r 2048..4095)
#define GAMMA_C 3.0f
#define LAMB_C 30.0f
#define TAU_C 10.0f
#define KCH 12         // 768 / 64 K-chunks in GEMM

// ---------------- scratch (device globals; no allocation allowed) ----------------
__device__ float g_tri[(size_t)TT * DD];
__device__ float g_att[4 * TT];              // exp(logit) per edge: [e0, e1, r0, r1]
__device__ float g_acc[(size_t)NN * DD];
__device__ float g_z[NN];
__device__ float g_feats[(size_t)NN * DD];
__device__ float g_out[(size_t)NN * OD];
__device__ float g_embsq[NN];
__device__ float g_asq[MR];
__device__ float g_pos[BB];
__device__ float g_dot[(size_t)MR * NJ];
__device__ float g_lse[MR];
// bf16 split operands for tensor-core GEMM
__device__ __align__(16) __nv_bfloat16 g_Ahi[(size_t)MR * OD];
__device__ __align__(16) __nv_bfloat16 g_Alo[(size_t)MR * OD];
__device__ __align__(16) __nv_bfloat16 g_Bhi[(size_t)NJ * OD];
__device__ __align__(16) __nv_bfloat16 g_Blo[(size_t)NJ * OD];

// ---------------- helpers ----------------
__device__ __forceinline__ float warp_sum_f(float v) {
#pragma unroll
    for (int o = 16; o; o >>= 1) v += __shfl_xor_sync(0xffffffffu, v, o);
    return v;
}
__device__ __forceinline__ uint32_t smem_u32(const void* p) {
    uint32_t a;
    asm("{ .reg .u64 t; cvta.to.shared.u64 t, %1; cvt.u32.u64 %0, t; }" : "=r"(a) : "l"(p));
    return a;
}
__device__ __forceinline__ uint32_t swz128(uint32_t b) { return b ^ ((b >> 3) & 0x70); }

__device__ __forceinline__ void cp16(uint32_t dst, const void* src) {
    asm volatile("cp.async.cg.shared.global [%0], [%1], 16;" :: "r"(dst), "l"(src));
}
#define CP_COMMIT() asm volatile("cp.async.commit_group;" ::: "memory")
#define CP_WAIT(n)  asm volatile("cp.async.wait_group %0;" :: "n"(n) : "memory")

__device__ __forceinline__ void ldsm4(uint32_t* r, uint32_t addr) {
    asm volatile("ldmatrix.sync.aligned.m8n8.x4.shared.b16 {%0,%1,%2,%3}, [%4];"
                 : "=r"(r[0]), "=r"(r[1]), "=r"(r[2]), "=r"(r[3]) : "r"(addr));
}
__device__ __forceinline__ void mma_bf16(float* c, const uint32_t* a, uint32_t b0, uint32_t b1) {
    asm volatile(
        "mma.sync.aligned.m16n8k16.row.col.f32.bf16.bf16.f32 "
        "{%0,%1,%2,%3}, {%4,%5,%6,%7}, {%8,%9}, {%0,%1,%2,%3};"
        : "+f"(c[0]), "+f"(c[1]), "+f"(c[2]), "+f"(c[3])
        : "r"(a[0]), "r"(a[1]), "r"(a[2]), "r"(a[3]), "r"(b0), "r"(b1));
}
// vectorized global float4 add-reduction (sm_90+, family-target safe)
__device__ __forceinline__ void red4(float* dst, float x, float y, float z, float w) {
    asm volatile("red.global.add.v4.f32 [%0], {%1, %2, %3, %4};"
                 :: "l"(dst), "f"(x), "f"(y), "f"(z), "f"(w) : "memory");
}

// ---------------- fill ----------------
__global__ void k_fill(int which) {
    size_t n = (which == 0) ? (size_t)NN * DD : (size_t)NN;
    float* p = (which == 0) ? g_acc : g_z;
    size_t i = (size_t)blockIdx.x * blockDim.x + threadIdx.x;
    if (i < n) p[i] = 0.0f;
}

// ---------------- tri_rel direct (r_index[0] == arange) + exp(att logits) ----------------
__global__ void k_tri_direct(const int* __restrict__ r1, const float* __restrict__ rval,
                             const float* __restrict__ rel_emb,
                             const float* __restrict__ attn_e, const float* __restrict__ attn_r) {
    int warp = (int)(((size_t)blockIdx.x * blockDim.x + threadIdx.x) >> 5);
    int lane = threadIdx.x & 31;
    if (warp >= TT) return;
    int rel = r1[warp];
    float v = rval[warp];
    float4 a = ((const float4*)(rel_emb + (size_t)rel * DD))[lane];
    a.x *= v; a.y *= v; a.z *= v; a.w *= v;
    float ss = a.x * a.x + a.y * a.y + a.z * a.z + a.w * a.w;
    ss = warp_sum_f(ss);
    float inv = 1.0f / fmaxf(sqrtf(ss), 1e-12f);
    a.x *= inv; a.y *= inv; a.z *= inv; a.w *= inv;
    ((float4*)(g_tri + (size_t)warp * DD))[lane] = a;

    float4 k0 = ((const float4*)attn_e)[lane];
    float4 k1 = ((const float4*)(attn_e + DD))[lane];
    float4 k2 = ((const float4*)attn_r)[lane];
    float4 k3 = ((const float4*)(attn_r + DD))[lane];
    float d0 = a.x * k0.x + a.y * k0.y + a.z * k0.z + a.w * k0.w;
    float d1 = a.x * k1.x + a.y * k1.y + a.z * k1.z + a.w * k1.w;
    float d2 = a.x * k2.x + a.y * k2.y + a.z * k2.z + a.w * k2.w;
    float d3 = a.x * k3.x + a.y * k3.y + a.z * k3.z + a.w * k3.w;
    d0 = warp_sum_f(d0);
    d1 = warp_sum_f(d1);
    d2 = warp_sum_f(d2);
    d3 = warp_sum_f(d3);
    if (lane == 0) {
        g_att[0 * TT + warp] = expf(d0);
        g_att[1 * TT + warp] = expf(d1);
        g_att[2 * TT + warp] = expf(d2);
        g_att[3 * TT + warp] = expf(d3);
    }
}

// ---------------- sparse_mean scatter (vector red) ----------------
__global__ void k_scatter_mean(const int* __restrict__ adj, const float* __restrict__ emb) {
    int warp = (int)(((size_t)blockIdx.x * blockDim.x + threadIdx.x) >> 5);
    int lane = threadIdx.x & 31;
    if (warp >= TT) return;
    int row = adj[warp];
    int col = adj[TT + warp];
    float4 a = ((const float4*)(emb + (size_t)col * DD))[lane];
    red4(g_acc + (size_t)row * DD + lane * 4, a.x, a.y, a.z, a.w);
    if (lane == 0) atomicAdd(&g_z[row], 1.0f);
}

// finalize mean; zeroes g_acc for next accumulation phase
__global__ void k_finalize_mean(int colofs) {
    size_t idx = (size_t)blockIdx.x * blockDim.x + threadIdx.x;
    if (idx >= (size_t)NN * DD) return;
    int n = (int)(idx / DD);
    int d = (int)(idx % DD);
    float c = fmaxf(g_z[n], 1.0f);
    float f = tanhf(g_acc[idx] / c);
    g_acc[idx] = 0.0f;
    g_feats[idx] = f;
    g_out[(size_t)n * OD + colofs + d] = f;
}

// ---------------- GAT softmax denominator (att already exp'd) ----------------
__global__ void k_zsum(const int* __restrict__ adj, int attofs) {
    int e = blockIdx.x * blockDim.x + threadIdx.x;
    if (e >= TT) return;
    atomicAdd(&g_z[adj[e]], g_att[attofs + e]);
}

// ---------------- GAT reflected-neighbor weighted scatter (vector red) ----------------
__global__ void k_reflect(const int* __restrict__ adj, int attofs) {
    int warp = (int)(((size_t)blockIdx.x * blockDim.x + threadIdx.x) >> 5);
    int lane = threadIdx.x & 31;
    if (warp >= TT) return;
    int row = adj[warp];
    int col = adj[TT + warp];
    float w = g_att[attofs + warp] / g_z[row];
    float4 t = ((const float4*)(g_tri + (size_t)warp * DD))[lane];
    float4 nb = ((const float4*)(g_feats + (size_t)col * DD))[lane];
    float s = nb.x * t.x + nb.y * t.y + nb.z * t.z + nb.w * t.w;
    s = warp_sum_f(s);
    float c2 = 2.0f * s;
    red4(g_acc + (size_t)row * DD + lane * 4,
         w * (nb.x - c2 * t.x), w * (nb.y - c2 * t.y),
         w * (nb.z - c2 * t.z), w * (nb.w - c2 * t.w));
}

// finalize tanh; zeroes g_acc for next phase
__global__ void k_finalize_tanh(int colofs) {
    size_t idx = (size_t)blockIdx.x * blockDim.x + threadIdx.x;
    if (idx >= (size_t)NN * DD) return;
    int n = (int)(idx / DD);
    int d = (int)(idx % DD);
    float f = tanhf(g_acc[idx]);
    g_acc[idx] = 0.0f;
    g_feats[idx] = f;
    g_out[(size_t)n * OD + colofs + d] = f;
}

// ---------------- B conversion + row squared norms (warp per row) ----------------
__global__ void k_cvtB_embsq() {
    int row = (int)(((size_t)blockIdx.x * blockDim.x + threadIdx.x) >> 5);
    int lane = threadIdx.x & 31;
    if (row >= NJ) return;
    float ss = 0.0f;
    if (row < NN) {
        const float4* p = (const float4*)(g_out + (size_t)row * OD);
#pragma unroll
        for (int j = lane; j < OD / 4; j += 32) {
            float4 a = p[j];
            ss += a.x * a.x + a.y * a.y + a.z * a.z + a.w * a.w;
            size_t o = (size_t)row * OD + j * 4;
            float v[4] = {a.x, a.y, a.z, a.w};
#pragma unroll
            for (int q = 0; q < 4; q++) {
                __nv_bfloat16 h = __float2bfloat16(v[q]);
                g_Bhi[o + q] = h;
                g_Blo[o + q] = __float2bfloat16(v[q] - __bfloat162float(h));
            }
        }
        ss = warp_sum_f(ss);
        if (lane == 0) g_embsq[row] = ss;
    } else {
        size_t o = (size_t)row * OD;
        for (int j = lane * 4; j < OD; j += 128) {
#pragma unroll
            for (int q = 0; q < 4; q++) {
                g_Bhi[o + j + q] = __float2bfloat16(0.0f);
                g_Blo[o + j + q] = __float2bfloat16(0.0f);
            }
        }
    }
}

// ---------------- gather A (writes bf16 split directly) + pos + asq ----------------
__global__ void k_pairprep(const int* __restrict__ pairs) {
    int i = blockIdx.x;
    int li = pairs[2 * i];
    int ri = pairs[2 * i + 1];
    const float* L = g_out + (size_t)li * OD;
    const float* R = g_out + (size_t)ri * OD;
    float part = 0.0f;
    for (int c = threadIdx.x; c < OD; c += 256) {
        float a = L[c];
        float b = R[c];
        __nv_bfloat16 ha = __float2bfloat16(a);
        __nv_bfloat16 hb = __float2bfloat16(b);
        size_t oa = (size_t)i * OD + c;
        size_t ob = (size_t)(i + BB) * OD + c;
        g_Ahi[oa] = ha;
        g_Alo[oa] = __float2bfloat16(a - __bfloat162float(ha));
        g_Ahi[ob] = hb;
        g_Alo[ob] = __float2bfloat16(b - __bfloat162float(hb));
        float d = a - b;
        part += d * d;
    }
    __shared__ float sh[8];
    int lane = threadIdx.x & 31, wid = threadIdx.x >> 5;
    part = warp_sum_f(part);
    if (lane == 0) sh[wid] = part;
    __syncthreads();
    if (threadIdx.x == 0) {
        float s = 0.0f;
        for (int w = 0; w < 8; w++) s += sh[w];
        g_pos[i] = s;
        g_asq[i] = g_embsq[li];
        g_asq[i + BB] = g_embsq[ri];
    }
}

// ---------------- mma.sync bf16x3 GEMM: g_dot = A @ B^T (3-stage cp.async) ----------------
__global__ __launch_bounds__(256, 1) void k_gemm_tc() {
    extern __shared__ char smraw[];
    uint32_t sm0 = smem_u32(smraw);
    uint32_t smbase = (sm0 + 1023u) & ~1023u;

    const int tid = threadIdx.x;
    const int warp = tid >> 5;
    const int lane = tid & 31;
    const int bi = blockIdx.x;   // M tile (0..31)
    const int bj = blockIdx.y;   // N tile (0..234)

    const uint4* srcs[4];
    srcs[0] = (const uint4*)g_Ahi + (size_t)(bi * 128) * 96;
    srcs[1] = (const uint4*)g_Alo + (size_t)(bi * 128) * 96;
    srcs[2] = (const uint4*)g_Bhi + (size_t)(bj * 128) * 96;
    srcs[3] = (const uint4*)g_Blo + (size_t)(bj * 128) * 96;

    const int frow = tid >> 3;       // 0..31
    const int fc = tid & 7;          // 16B chunk in 128B row
#define FILL_STAGE(kc, stage)                                                    \
    do {                                                                         \
        uint32_t st_ = smbase + (uint32_t)(stage) * 65536u;                      \
        _Pragma("unroll")                                                        \
        for (int m_ = 0; m_ < 4; m_++) {                                         \
            const uint4* src_ = srcs[m_];                                        \
            uint32_t tb_ = st_ + m_ * 16384u;                                    \
            _Pragma("unroll")                                                    \
            for (int i_ = 0; i_ < 4; i_++) {                                     \
                int row_ = frow + i_ * 32;                                       \
                cp16(tb_ + swz128((uint32_t)(row_ * 128 + fc * 16)),             \
                     src_ + (size_t)row_ * 96 + (kc) * 8 + fc);                  \
            }                                                                    \
        }                                                                        \
        CP_COMMIT();                                                             \
    } while (0)

    const int wm = warp >> 2;        // 0..1
    const int wn = warp & 3;         // 0..3
    uint32_t mrow[4], brow[2];
#pragma unroll
    for (int mi = 0; mi < 4; mi++)
        mrow[mi] = (uint32_t)((wm * 64 + mi * 16 + (lane & 15)) * 128);
#pragma unroll
    for (int g = 0; g < 2; g++)
        brow[g] = (uint32_t)((wn * 32 + g * 16 + (lane & 7) + ((lane >> 3) & 1) * 8) * 128);
    const uint32_t csel = (uint32_t)(((lane >> 4) & 1) * 16);

    float acc[4][4][4];
#pragma unroll
    for (int mi = 0; mi < 4; mi++)
#pragma unroll
        for (int nj = 0; nj < 4; nj++)
#pragma unroll
            for (int q = 0; q < 4; q++) acc[mi][nj][q] = 0.0f;

    FILL_STAGE(0, 0);
    FILL_STAGE(1, 1);

    for (int k = 0; k < KCH; k++) {
        if (k + 1 < KCH) CP_WAIT(1);
        else CP_WAIT(0);
        __syncthreads();
        if (k + 2 < KCH) FILL_STAGE(k + 2, (k + 2) % 3);

        int s = k % 3;
        uint32_t Ahb = smbase + (uint32_t)s * 65536u;
        uint32_t Alb = Ahb + 16384u;
        uint32_t Bhb = Ahb + 32768u;
        uint32_t Blb = Ahb + 49152u;
#pragma unroll
        for (int ks = 0; ks < 4; ks++) {
            uint32_t col = (uint32_t)(ks * 32) + csel;
            uint32_t ahi[4][4], alo[4][4], bhi[2][4], blo[2][4];
#pragma unroll
            for (int mi = 0; mi < 4; mi++) {
                uint32_t so = swz128(mrow[mi] + col);
                ldsm4(ahi[mi], Ahb + so);
                ldsm4(alo[mi], Alb + so);
            }
#pragma unroll
            for (int g = 0; g < 2; g++) {
                uint32_t so = swz128(brow[g] + col);
                ldsm4(bhi[g], Bhb + so);
                ldsm4(blo[g], Blb + so);
            }
#pragma unroll
            for (int mi = 0; mi < 4; mi++) {
#pragma unroll
                for (int nj = 0; nj < 4; nj++) {
                    int g = nj >> 1, h = nj & 1;
                    mma_bf16(acc[mi][nj], ahi[mi], bhi[g][h], bhi[g][h + 2]);
                    mma_bf16(acc[mi][nj], ahi[mi], blo[g][h], blo[g][h + 2]);
                    mma_bf16(acc[mi][nj], alo[mi], bhi[g][h], bhi[g][h + 2]);
                }
            }
        }
    }

    const int mrow0 = bi * 128 + wm * 64;
    const int ncol0 = bj * 128 + wn * 32;
    const int rofs = lane >> 2;
    const int cofs = (lane & 3) * 2;
#pragma unroll
    for (int mi = 0; mi < 4; mi++) {
#pragma unroll
        for (int nj = 0; nj < 4; nj++) {
            size_t r0 = (size_t)(mrow0 + mi * 16 + rofs);
            size_t c0 = (size_t)(ncol0 + nj * 8 + cofs);
            float2 v0 = make_float2(acc[mi][nj][0], acc[mi][nj][1]);
            float2 v1 = make_float2(acc[mi][nj][2], acc[mi][nj][3]);
            *(float2*)(g_dot + r0 * NJ + c0) = v0;
            *(float2*)(g_dot + (r0 + 8) * NJ + c0) = v1;
        }
    }
#undef FILL_STAGE
}

// ---------------- fused loss pass: stats + logsumexp, row cached in SMEM ----------------
// One CTA (512 thr) per row i. lv values computed once into smem; exp skipped when
// contribution < e^-21 (bounded total error < 7e-5 relative on the sum).
__global__ __launch_bounds__(512) void k_pass(const int* __restrict__ pairs) {
    extern __shared__ float srow[];   // NN floats
    const int i = blockIdx.x;
    const int p = i & (BB - 1);
    const int li = pairs[2 * p];
    const int ri = pairs[2 * p + 1];
    const float posg = g_pos[p] + GAMMA_C;
    const float asq = g_asq[i];
    const float* drow = g_dot + (size_t)i * NJ;

    double s = 0.0, s2 = 0.0;
    float mx = -3.4e38f;
    for (int j = threadIdx.x; j < NN; j += 512) {
        float neg = asq + g_embsq[j] - 2.0f * drow[j];
        float lv = posg - neg;
        float fac = 1.0f - (float)(j == li) - (float)(j == ri);
        lv *= fac;
        srow[j] = lv;
        s += lv;
        s2 += (double)lv * (double)lv;
        mx = fmaxf(mx, lv);
    }
    __shared__ double sh_s[16], sh_s2[16];
    __shared__ float sh_m[16];
    __shared__ float bc_mu, bc_sc, bc_Mt;
    int lane = threadIdx.x & 31, wid = threadIdx.x >> 5;
#pragma unroll
    for (int o = 16; o; o >>= 1) {
        s += __shfl_xor_sync(0xffffffffu, s, o);
        s2 += __shfl_xor_sync(0xffffffffu, s2, o);
        mx = fmaxf(mx, __shfl_xor_sync(0xffffffffu, mx, o));
    }
    if (lane == 0) { sh_s[wid] = s; sh_s2[wid] = s2; sh_m[wid] = mx; }
    __syncthreads();
    if (threadIdx.x == 0) {
        double S = 0.0, S2 = 0.0;
        float M = -3.4e38f;
        for (int w = 0; w < 16; w++) { S += sh_s[w]; S2 += sh_s2[w]; M = fmaxf(M, sh_m[w]); }
        double mu = S / (double)NN;
        double var = S2 / (double)NN - mu * mu;
        if (var < 0.0) var = 0.0;
        float sd = (float)fmax(sqrt(var), 1e-30);
        bc_mu = (float)mu;
        bc_sc = LAMB_C / sd;
        bc_Mt = (LAMB_C / sd) * (M - (float)mu);
    }
    __syncthreads();
    const float mu = bc_mu, sc = bc_sc, Mt = bc_Mt;

    double se = 0.0;
    for (int j = threadIdx.x; j < NN; j += 512) {
        float t = sc * (srow[j] - mu) - Mt;
        if (t > -21.0f) se += (double)__expf(t);
    }
#pragma unroll
    for (int o = 16; o; o >>= 1) se += __shfl_xor_sync(0xffffffffu, se, o);
    if (lane == 0) sh_s[wid] = se;
    __syncthreads();
    if (threadIdx.x == 0) {
        double S = 0.0;
        for (int w = 0; w < 16; w++) S += sh_s[w];
        g_lse[i] = (float)((double)Mt + TAU_C + log(S));
    }
}

// ---------------- final mean ----------------
__global__ void k_final(float* __restrict__ out, int out_size) {
    double s = 0.0;
    for (int i = threadIdx.x; i < MR; i += 256) s += (double)g_lse[i];
    __shared__ double sh[8];
    int lane = threadIdx.x & 31, wid = threadIdx.x >> 5;
#pragma unroll
    for (int o = 16; o; o >>= 1) s += __shfl_xor_sync(0xffffffffu, s, o);
    if (lane == 0) sh[wid] = s;
    __syncthreads();
    if (threadIdx.x == 0) {
        double S = 0.0;
        for (int w = 0; w < 8; w++) S += sh[w];
        float val = (float)(S / (double)BB);
        for (int k = 0; k < out_size; k++) out[k] = val;
    }
}

// ---------------- host launch ----------------
extern "C" void kernel_launch(void* const* d_in, const int* in_sizes, int n_in,
                              void* d_out, int out_size) {
    const int* pairs = (const int*)d_in[0];
    const int* ent_adj = (const int*)d_in[1];
    const int* rel_adj = (const int*)d_in[2];
    const int* adj_list = (const int*)d_in[3];
    const int* r_index = (const int*)d_in[4];
    const float* r_val = (const float*)d_in[5];
    const float* ent_emb = (const float*)d_in[7];
    const float* rel_emb = (const float*)d_in[8];
    const float* attn_e = (const float*)d_in[9];
    const float* attn_r = (const float*)d_in[10];
    float* out = (float*)d_out;

    const int NT = 256;
    const int gb_acc = (int)(((size_t)NN * DD + NT - 1) / NT);
    const int gb_z = (NN + NT - 1) / NT;
    const int gb_ew = (int)(((size_t)TT * 32 + NT - 1) / NT);
    const int gb_et = (TT + NT - 1) / NT;
    const int gb_nw = (int)(((size_t)NJ * 32 + NT - 1) / NT);

    // tri_rel direct (identity segments) + attention exp-logits
    k_tri_direct<<<gb_ew, NT>>>(r_index + TT, r_val, rel_emb, attn_e, attn_r);

    // ---- GAT over ent_feature ----
    k_fill<<<gb_acc, NT>>>(0);   // only explicit acc zero; finalizers re-zero
    k_fill<<<gb_z, NT>>>(1);
    k_scatter_mean<<<gb_ew, NT>>>(ent_adj, ent_emb);
    k_finalize_mean<<<gb_acc, NT>>>(0);
    for (int l = 0; l < 2; l++) {
        k_fill<<<gb_z, NT>>>(1);
        k_zsum<<<gb_et, NT>>>(adj_list, l * TT);
        k_reflect<<<gb_ew, NT>>>(adj_list, l * TT);
        k_finalize_tanh<<<gb_acc, NT>>>((l + 1) * DD);
    }

    // ---- GAT over rel_feature ----
    k_fill<<<gb_z, NT>>>(1);
    k_scatter_mean<<<gb_ew, NT>>>(rel_adj, rel_emb);
    k_finalize_mean<<<gb_acc, NT>>>(3 * DD);
    for (int l = 0; l < 2; l++) {
        k_fill<<<gb_z, NT>>>(1);
        k_zsum<<<gb_et, NT>>>(adj_list, (2 + l) * TT);
        k_reflect<<<gb_ew, NT>>>(adj_list, (2 + l) * TT);
        k_finalize_tanh<<<gb_acc, NT>>>((4 + l) * DD);
    }

    // ---- align loss ----
    k_cvtB_embsq<<<gb_nw, NT>>>();
    k_pairprep<<<BB, NT>>>(pairs);

    const int gemm_smem = 3 * 65536 + 1024;
    cudaFuncSetAttribute(k_gemm_tc, cudaFuncAttributeMaxDynamicSharedMemorySize, gemm_smem);
    dim3 gg(MR / 128, NJ / 128);  // x = M tiles fastest -> B tile reuse in L2
    k_gemm_tc<<<gg, 256, gemm_smem>>>();

    const int pass_smem = NN * (int)sizeof(float);
    cudaFuncSetAttribute(k_pass, cudaFuncAttributeMaxDynamicSharedMemorySize, pass_smem);
    k_pass<<<MR, 512, pass_smem>>>(pairs);
    k_final<<<1, 256>>>(out, out_size);
}

// round 9
// speedup vs baseline: 1.1768x; 1.1512x over previous
#include <cuda_runtime.h>
#include <cuda_fp16.h>
#include <math.h>
#include <stdint.h>

// Problem constants
#define NN 30000       // node_size
#define RR 1000        // rel_size
#define TT 200000      // triple_size
#define DD 128         // DIM
#define BB 2048        // BATCH
#define OD 768         // output feature dim (6 * 128)
#define NJ 30080       // padded column count for dot matrix (235*128)
#define MR 4096        // stacked query rows (l 0..2047, r 2048..4095)
#define GAMMA_C 3.0f
#define LAMB_C 30.0f
#define TAU_C 10.0f
#define KCH 12         // 768 / 64 K-chunks in GEMM

// ---------------- scratch (device globals; no allocation allowed) ----------------
__device__ float g_tri[(size_t)TT * DD];
__device__ float g_att[4 * TT];              // exp(logit) per edge: [e0, e1, r0, r1]
__device__ float g_acc[(size_t)NN * DD];
__device__ float g_z[NN];
__device__ float g_feats[(size_t)NN * DD];
__device__ float g_out[(size_t)NN * OD];
__device__ float g_embsq[NN];
__device__ float g_asq[MR];
__device__ float g_pos[BB];
__device__ float g_dot[(size_t)MR * NJ];
__device__ float g_lse[MR];
// fp16 split operands for tensor-core GEMM: A = Ahi + Alo (exact to 2^-22), B = Bh (round)
__device__ __align__(16) __half g_Ahi[(size_t)MR * OD];
__device__ __align__(16) __half g_Alo[(size_t)MR * OD];
__device__ __align__(16) __half g_Bh[(size_t)NJ * OD];

// ---------------- helpers ----------------
__device__ __forceinline__ float warp_sum_f(float v) {
#pragma unroll
    for (int o = 16; o; o >>= 1) v += __shfl_xor_sync(0xffffffffu, v, o);
    return v;
}
__device__ __forceinline__ uint32_t smem_u32(const void* p) {
    uint32_t a;
    asm("{ .reg .u64 t; cvta.to.shared.u64 t, %1; cvt.u32.u64 %0, t; }" : "=r"(a) : "l"(p));
    return a;
}
__device__ __forceinline__ uint32_t swz128(uint32_t b) { return b ^ ((b >> 3) & 0x70); }

__device__ __forceinline__ void cp16(uint32_t dst, const void* src) {
    asm volatile("cp.async.cg.shared.global [%0], [%1], 16;" :: "r"(dst), "l"(src));
}
#define CP_COMMIT() asm volatile("cp.async.commit_group;" ::: "memory")
#define CP_WAIT(n)  asm volatile("cp.async.wait_group %0;" :: "n"(n) : "memory")

__device__ __forceinline__ void ldsm4(uint32_t* r, uint32_t addr) {
    asm volatile("ldmatrix.sync.aligned.m8n8.x4.shared.b16 {%0,%1,%2,%3}, [%4];"
                 : "=r"(r[0]), "=r"(r[1]), "=r"(r[2]), "=r"(r[3]) : "r"(addr));
}
__device__ __forceinline__ void mma_f16(float* c, const uint32_t* a, uint32_t b0, uint32_t b1) {
    asm volatile(
        "mma.sync.aligned.m16n8k16.row.col.f32.f16.f16.f32 "
        "{%0,%1,%2,%3}, {%4,%5,%6,%7}, {%8,%9}, {%0,%1,%2,%3};"
        : "+f"(c[0]), "+f"(c[1]), "+f"(c[2]), "+f"(c[3])
        : "r"(a[0]), "r"(a[1]), "r"(a[2]), "r"(a[3]), "r"(b0), "r"(b1));
}
// vectorized global float4 add-reduction
__device__ __forceinline__ void red4(float* dst, float x, float y, float z, float w) {
    asm volatile("red.global.add.v4.f32 [%0], {%1, %2, %3, %4};"
                 :: "l"(dst), "f"(x), "f"(y), "f"(z), "f"(w) : "memory");
}

// ---------------- fill ----------------
__global__ void k_fill(int which) {
    size_t n = (which == 0) ? (size_t)NN * DD : (size_t)NN;
    float* p = (which == 0) ? g_acc : g_z;
    size_t i = (size_t)blockIdx.x * blockDim.x + threadIdx.x;
    if (i < n) p[i] = 0.0f;
}

// ---------------- tri_rel direct (r_index[0] == arange) + exp(att logits) ----------------
__global__ void k_tri_direct(const int* __restrict__ r1, const float* __restrict__ rval,
                             const float* __restrict__ rel_emb,
                             const float* __restrict__ attn_e, const float* __restrict__ attn_r) {
    int warp = (int)(((size_t)blockIdx.x * blockDim.x + threadIdx.x) >> 5);
    int lane = threadIdx.x & 31;
    if (warp >= TT) return;
    int rel = r1[warp];
    float v = rval[warp];
    float4 a = ((const float4*)(rel_emb + (size_t)rel * DD))[lane];
    a.x *= v; a.y *= v; a.z *= v; a.w *= v;
    float ss = a.x * a.x + a.y * a.y + a.z * a.z + a.w * a.w;
    ss = warp_sum_f(ss);
    float inv = 1.0f / fmaxf(sqrtf(ss), 1e-12f);
    a.x *= inv; a.y *= inv; a.z *= inv; a.w *= inv;
    ((float4*)(g_tri + (size_t)warp * DD))[lane] = a;

    float4 k0 = ((const float4*)attn_e)[lane];
    float4 k1 = ((const float4*)(attn_e + DD))[lane];
    float4 k2 = ((const float4*)attn_r)[lane];
    float4 k3 = ((const float4*)(attn_r + DD))[lane];
    float d0 = a.x * k0.x + a.y * k0.y + a.z * k0.z + a.w * k0.w;
    float d1 = a.x * k1.x + a.y * k1.y + a.z * k1.z + a.w * k1.w;
    float d2 = a.x * k2.x + a.y * k2.y + a.z * k2.z + a.w * k2.w;
    float d3 = a.x * k3.x + a.y * k3.y + a.z * k3.z + a.w * k3.w;
    d0 = warp_sum_f(d0);
    d1 = warp_sum_f(d1);
    d2 = warp_sum_f(d2);
    d3 = warp_sum_f(d3);
    if (lane == 0) {
        g_att[0 * TT + warp] = expf(d0);
        g_att[1 * TT + warp] = expf(d1);
        g_att[2 * TT + warp] = expf(d2);
        g_att[3 * TT + warp] = expf(d3);
    }
}

// ---------------- sparse_mean scatter (vector red) ----------------
__global__ void k_scatter_mean(const int* __restrict__ adj, const float* __restrict__ emb) {
    int warp = (int)(((size_t)blockIdx.x * blockDim.x + threadIdx.x) >> 5);
    int lane = threadIdx.x & 31;
    if (warp >= TT) return;
    int row = adj[warp];
    int col = adj[TT + warp];
    float4 a = ((const float4*)(emb + (size_t)col * DD))[lane];
    red4(g_acc + (size_t)row * DD + lane * 4, a.x, a.y, a.z, a.w);
    if (lane == 0) atomicAdd(&g_z[row], 1.0f);
}

// finalize mean; zeroes g_acc for next accumulation phase
__global__ void k_finalize_mean(int colofs) {
    size_t idx = (size_t)blockIdx.x * blockDim.x + threadIdx.x;
    if (idx >= (size_t)NN * DD) return;
    int n = (int)(idx / DD);
    int d = (int)(idx % DD);
    float c = fmaxf(g_z[n], 1.0f);
    float f = tanhf(g_acc[idx] / c);
    g_acc[idx] = 0.0f;
    g_feats[idx] = f;
    g_out[(size_t)n * OD + colofs + d] = f;
}

// ---------------- GAT softmax denominator (att already exp'd) ----------------
__global__ void k_zsum(const int* __restrict__ adj, int attofs) {
    int e = blockIdx.x * blockDim.x + threadIdx.x;
    if (e >= TT) return;
    atomicAdd(&g_z[adj[e]], g_att[attofs + e]);
}

// ---------------- GAT reflected-neighbor weighted scatter (vector red) ----------------
__global__ void k_reflect(const int* __restrict__ adj, int attofs) {
    int warp = (int)(((size_t)blockIdx.x * blockDim.x + threadIdx.x) >> 5);
    int lane = threadIdx.x & 31;
    if (warp >= TT) return;
    int row = adj[warp];
    int col = adj[TT + warp];
    float w = g_att[attofs + warp] / g_z[row];
    float4 t = ((const float4*)(g_tri + (size_t)warp * DD))[lane];
    float4 nb = ((const float4*)(g_feats + (size_t)col * DD))[lane];
    float s = nb.x * t.x + nb.y * t.y + nb.z * t.z + nb.w * t.w;
    s = warp_sum_f(s);
    float c2 = 2.0f * s;
    red4(g_acc + (size_t)row * DD + lane * 4,
         w * (nb.x - c2 * t.x), w * (nb.y - c2 * t.y),
         w * (nb.z - c2 * t.z), w * (nb.w - c2 * t.w));
}

// finalize tanh; zeroes g_acc for next phase
__global__ void k_finalize_tanh(int colofs) {
    size_t idx = (size_t)blockIdx.x * blockDim.x + threadIdx.x;
    if (idx >= (size_t)NN * DD) return;
    int n = (int)(idx / DD);
    int d = (int)(idx % DD);
    float f = tanhf(g_acc[idx]);
    g_acc[idx] = 0.0f;
    g_feats[idx] = f;
    g_out[(size_t)n * OD + colofs + d] = f;
}

// ---------------- B conversion (single fp16 round) + row squared norms ----------------
__global__ void k_cvtB_embsq() {
    int row = (int)(((size_t)blockIdx.x * blockDim.x + threadIdx.x) >> 5);
    int lane = threadIdx.x & 31;
    if (row >= NJ) return;
    float ss = 0.0f;
    if (row < NN) {
        const float4* p = (const float4*)(g_out + (size_t)row * OD);
#pragma unroll
        for (int j = lane; j < OD / 4; j += 32) {
            float4 a = p[j];
            ss += a.x * a.x + a.y * a.y + a.z * a.z + a.w * a.w;
            size_t o = (size_t)row * OD + j * 4;
            g_Bh[o + 0] = __float2half_rn(a.x);
            g_Bh[o + 1] = __float2half_rn(a.y);
            g_Bh[o + 2] = __float2half_rn(a.z);
            g_Bh[o + 3] = __float2half_rn(a.w);
        }
        ss = warp_sum_f(ss);
        if (lane == 0) g_embsq[row] = ss;
    } else {
        size_t o = (size_t)row * OD;
        for (int j = lane * 4; j < OD; j += 128) {
#pragma unroll
            for (int q = 0; q < 4; q++) g_Bh[o + j + q] = __float2half_rn(0.0f);
        }
    }
}

// ---------------- gather A (fp16 hi/lo split) + pos + asq ----------------
__global__ void k_pairprep(const int* __restrict__ pairs) {
    int i = blockIdx.x;
    int li = pairs[2 * i];
    int ri = pairs[2 * i + 1];
    const float* L = g_out + (size_t)li * OD;
    const float* R = g_out + (size_t)ri * OD;
    float part = 0.0f;
    for (int c = threadIdx.x; c < OD; c += 256) {
        float a = L[c];
        float b = R[c];
        __half ha = __float2half_rn(a);
        __half hb = __float2half_rn(b);
        size_t oa = (size_t)i * OD + c;
        size_t ob = (size_t)(i + BB) * OD + c;
        g_Ahi[oa] = ha;
        g_Alo[oa] = __float2half_rn(a - __half2float(ha));
        g_Ahi[ob] = hb;
        g_Alo[ob] = __float2half_rn(b - __half2float(hb));
        float d = a - b;
        part += d * d;
    }
    __shared__ float sh[8];
    int lane = threadIdx.x & 31, wid = threadIdx.x >> 5;
    part = warp_sum_f(part);
    if (lane == 0) sh[wid] = part;
    __syncthreads();
    if (threadIdx.x == 0) {
        float s = 0.0f;
        for (int w = 0; w < 8; w++) s += sh[w];
        g_pos[i] = s;
        g_asq[i] = g_embsq[li];
        g_asq[i + BB] = g_embsq[ri];
    }
}

// ---------------- mma.sync fp16x2 GEMM: g_dot = A @ B^T (3-stage cp.async) ----------------
// dot = Ahi*Bh + Alo*Bh ; dropped A*(B-Bh) residual ~2^-12 relative per element.
// Stage = Ah(16KB) + Al(16KB) + Bh(16KB) = 48KB; 3 stages.
__global__ __launch_bounds__(256, 1) void k_gemm_tc() {
    extern __shared__ char smraw[];
    uint32_t sm0 = smem_u32(smraw);
    uint32_t smbase = (sm0 + 1023u) & ~1023u;

    const int tid = threadIdx.x;
    const int warp = tid >> 5;
    const int lane = tid & 31;
    const int bi = blockIdx.x;   // M tile (0..31)
    const int bj = blockIdx.y;   // N tile (0..234)

    const uint4* srcs[3];
    srcs[0] = (const uint4*)g_Ahi + (size_t)(bi * 128) * 96;
    srcs[1] = (const uint4*)g_Alo + (size_t)(bi * 128) * 96;
    srcs[2] = (const uint4*)g_Bh + (size_t)(bj * 128) * 96;

    const int frow = tid >> 3;       // 0..31
    const int fc = tid & 7;          // 16B chunk in 128B row
#define FILL_STAGE(kc, stage)                                                    \
    do {                                                                         \
        uint32_t st_ = smbase + (uint32_t)(stage) * 49152u;                      \
        _Pragma("unroll")                                                        \
        for (int m_ = 0; m_ < 3; m_++) {                                         \
            const uint4* src_ = srcs[m_];                                        \
            uint32_t tb_ = st_ + m_ * 16384u;                                    \
            _Pragma("unroll")                                                    \
            for (int i_ = 0; i_ < 4; i_++) {                                     \
                int row_ = frow + i_ * 32;                                       \
                cp16(tb_ + swz128((uint32_t)(row_ * 128 + fc * 16)),             \
                     src_ + (size_t)row_ * 96 + (kc) * 8 + fc);                  \
            }                                                                    \
        }                                                                        \
        CP_COMMIT();                                                             \
    } while (0)

    const int wm = warp >> 2;        // 0..1
    const int wn = warp & 3;         // 0..3
    uint32_t mrow[4], brow[2];
#pragma unroll
    for (int mi = 0; mi < 4; mi++)
        mrow[mi] = (uint32_t)((wm * 64 + mi * 16 + (lane & 15)) * 128);
#pragma unroll
    for (int g = 0; g < 2; g++)
        brow[g] = (uint32_t)((wn * 32 + g * 16 + (lane & 7) + ((lane >> 3) & 1) * 8) * 128);
    const uint32_t csel = (uint32_t)(((lane >> 4) & 1) * 16);

    float acc[4][4][4];
#pragma unroll
    for (int mi = 0; mi < 4; mi++)
#pragma unroll
        for (int nj = 0; nj < 4; nj++)
#pragma unroll
            for (int q = 0; q < 4; q++) acc[mi][nj][q] = 0.0f;

    FILL_STAGE(0, 0);
    FILL_STAGE(1, 1);

    for (int k = 0; k < KCH; k++) {
        if (k + 1 < KCH) CP_WAIT(1);
        else CP_WAIT(0);
        __syncthreads();
        if (k + 2 < KCH) FILL_STAGE(k + 2, (k + 2) % 3);

        int s = k % 3;
        uint32_t Ahb = smbase + (uint32_t)s * 49152u;
        uint32_t Alb = Ahb + 16384u;
        uint32_t Bhb = Ahb + 32768u;
#pragma unroll
        for (int ks = 0; ks < 4; ks++) {
            uint32_t col = (uint32_t)(ks * 32) + csel;
            uint32_t ahi[4][4], alo[4][4], bh[2][4];
#pragma unroll
            for (int mi = 0; mi < 4; mi++) {
                uint32_t so = swz128(mrow[mi] + col);
                ldsm4(ahi[mi], Ahb + so);
                ldsm4(alo[mi], Alb + so);
            }
#pragma unroll
            for (int g = 0; g < 2; g++) {
                uint32_t so = swz128(brow[g] + col);
                ldsm4(bh[g], Bhb + so);
            }
#pragma unroll
            for (int mi = 0; mi < 4; mi++) {
#pragma unroll
                for (int nj = 0; nj < 4; nj++) {
                    int g = nj >> 1, h = nj & 1;
                    mma_f16(acc[mi][nj], ahi[mi], bh[g][h], bh[g][h + 2]);
                    mma_f16(acc[mi][nj], alo[mi], bh[g][h], bh[g][h + 2]);
                }
            }
        }
    }

    const int mrow0 = bi * 128 + wm * 64;
    const int ncol0 = bj * 128 + wn * 32;
    const int rofs = lane >> 2;
    const int cofs = (lane & 3) * 2;
#pragma unroll
    for (int mi = 0; mi < 4; mi++) {
#pragma unroll
        for (int nj = 0; nj < 4; nj++) {
            size_t r0 = (size_t)(mrow0 + mi * 16 + rofs);
            size_t c0 = (size_t)(ncol0 + nj * 8 + cofs);
            float2 v0 = make_float2(acc[mi][nj][0], acc[mi][nj][1]);
            float2 v1 = make_float2(acc[mi][nj][2], acc[mi][nj][3]);
            *(float2*)(g_dot + r0 * NJ + c0) = v0;
            *(float2*)(g_dot + (r0 + 8) * NJ + c0) = v1;
        }
    }
#undef FILL_STAGE
}

// ---------------- fused loss pass: stats + logsumexp, row cached in SMEM ----------------
__global__ __launch_bounds__(512) void k_pass(const int* __restrict__ pairs) {
    extern __shared__ float srow[];   // NN floats
    const int i = blockIdx.x;
    const int p = i & (BB - 1);
    const int li = pairs[2 * p];
    const int ri = pairs[2 * p + 1];
    const float posg = g_pos[p] + GAMMA_C;
    const float asq = g_asq[i];
    const float* drow = g_dot + (size_t)i * NJ;

    double s = 0.0, s2 = 0.0;
    float mx = -3.4e38f;
    for (int j = threadIdx.x; j < NN; j += 512) {
        float neg = asq + g_embsq[j] - 2.0f * drow[j];
        float lv = posg - neg;
        float fac = 1.0f - (float)(j == li) - (float)(j == ri);
        lv *= fac;
        srow[j] = lv;
        s += lv;
        s2 += (double)lv * (double)lv;
        mx = fmaxf(mx, lv);
    }
    __shared__ double sh_s[16], sh_s2[16];
    __shared__ float sh_m[16];
    __shared__ float bc_mu, bc_sc, bc_Mt;
    int lane = threadIdx.x & 31, wid = threadIdx.x >> 5;
#pragma unroll
    for (int o = 16; o; o >>= 1) {
        s += __shfl_xor_sync(0xffffffffu, s, o);
        s2 += __shfl_xor_sync(0xffffffffu, s2, o);
        mx = fmaxf(mx, __shfl_xor_sync(0xffffffffu, mx, o));
    }
    if (lane == 0) { sh_s[wid] = s; sh_s2[wid] = s2; sh_m[wid] = mx; }
    __syncthreads();
    if (threadIdx.x == 0) {
        double S = 0.0, S2 = 0.0;
        float M = -3.4e38f;
        for (int w = 0; w < 16; w++) { S += sh_s[w]; S2 += sh_s2[w]; M = fmaxf(M, sh_m[w]); }
        double mu = S / (double)NN;
        double var = S2 / (double)NN - mu * mu;
        if (var < 0.0) var = 0.0;
        float sd = (float)fmax(sqrt(var), 1e-30);
        bc_mu = (float)mu;
        bc_sc = LAMB_C / sd;
        bc_Mt = (LAMB_C / sd) * (M - (float)mu);
    }
    __syncthreads();
    const float mu = bc_mu, sc = bc_sc, Mt = bc_Mt;

    double se = 0.0;
    for (int j = threadIdx.x; j < NN; j += 512) {
        float t = sc * (srow[j] - mu) - Mt;
        if (t > -21.0f) se += (double)__expf(t);
    }
#pragma unroll
    for (int o = 16; o; o >>= 1) se += __shfl_xor_sync(0xffffffffu, se, o);
    if (lane == 0) sh_s[wid] = se;
    __syncthreads();
    if (threadIdx.x == 0) {
        double S = 0.0;
        for (int w = 0; w < 16; w++) S += sh_s[w];
        g_lse[i] = (float)((double)Mt + TAU_C + log(S));
    }
}

// ---------------- final mean ----------------
__global__ void k_final(float* __restrict__ out, int out_size) {
    double s = 0.0;
    for (int i = threadIdx.x; i < MR; i += 256) s += (double)g_lse[i];
    __shared__ double sh[8];
    int lane = threadIdx.x & 31, wid = threadIdx.x >> 5;
#pragma unroll
    for (int o = 16; o; o >>= 1) s += __shfl_xor_sync(0xffffffffu, s, o);
    if (lane == 0) sh[wid] = s;
    __syncthreads();
    if (threadIdx.x == 0) {
        double S = 0.0;
        for (int w = 0; w < 8; w++) S += sh[w];
        float val = (float)(S / (double)BB);
        for (int k = 0; k < out_size; k++) out[k] = val;
    }
}

// ---------------- host launch ----------------
extern "C" void kernel_launch(void* const* d_in, const int* in_sizes, int n_in,
                              void* d_out, int out_size) {
    const int* pairs = (const int*)d_in[0];
    const int* ent_adj = (const int*)d_in[1];
    const int* rel_adj = (const int*)d_in[2];
    const int* adj_list = (const int*)d_in[3];
    const int* r_index = (const int*)d_in[4];
    const float* r_val = (const float*)d_in[5];
    const float* ent_emb = (const float*)d_in[7];
    const float* rel_emb = (const float*)d_in[8];
    const float* attn_e = (const float*)d_in[9];
    const float* attn_r = (const float*)d_in[10];
    float* out = (float*)d_out;

    const int NT = 256;
    const int gb_acc = (int)(((size_t)NN * DD + NT - 1) / NT);
    const int gb_z = (NN + NT - 1) / NT;
    const int gb_ew = (int)(((size_t)TT * 32 + NT - 1) / NT);
    const int gb_et = (TT + NT - 1) / NT;
    const int gb_nw = (int)(((size_t)NJ * 32 + NT - 1) / NT);

    // tri_rel direct (identity segments) + attention exp-logits
    k_tri_direct<<<gb_ew, NT>>>(r_index + TT, r_val, rel_emb, attn_e, attn_r);

    // ---- GAT over ent_feature ----
    k_fill<<<gb_acc, NT>>>(0);   // only explicit acc zero; finalizers re-zero
    k_fill<<<gb_z, NT>>>(1);
    k_scatter_mean<<<gb_ew, NT>>>(ent_adj, ent_emb);
    k_finalize_mean<<<gb_acc, NT>>>(0);
    for (int l = 0; l < 2; l++) {
        k_fill<<<gb_z, NT>>>(1);
        k_zsum<<<gb_et, NT>>>(adj_list, l * TT);
        k_reflect<<<gb_ew, NT>>>(adj_list, l * TT);
        k_finalize_tanh<<<gb_acc, NT>>>((l + 1) * DD);
    }

    // ---- GAT over rel_feature ----
    k_fill<<<gb_z, NT>>>(1);
    k_scatter_mean<<<gb_ew, NT>>>(rel_adj, rel_emb);
    k_finalize_mean<<<gb_acc, NT>>>(3 * DD);
    for (int l = 0; l < 2; l++) {
        k_fill<<<gb_z, NT>>>(1);
        k_zsum<<<gb_et, NT>>>(adj_list, (2 + l) * TT);
        k_reflect<<<gb_ew, NT>>>(adj_list, (2 + l) * TT);
        k_finalize_tanh<<<gb_acc, NT>>>((4 + l) * DD);
    }

    // ---- align loss ----
    k_cvtB_embsq<<<gb_nw, NT>>>();
    k_pairprep<<<BB, NT>>>(pairs);

    const int gemm_smem = 3 * 49152 + 1024;
    cudaFuncSetAttribute(k_gemm_tc, cudaFuncAttributeMaxDynamicSharedMemorySize, gemm_smem);
    dim3 gg(MR / 128, NJ / 128);  // x = M tiles fastest -> B tile reuse in L2
    k_gemm_tc<<<gg, 256, gemm_smem>>>();

    const int pass_smem = NN * (int)sizeof(float);
    cudaFuncSetAttribute(k_pass, cudaFuncAttributeMaxDynamicSharedMemorySize, pass_smem);
    k_pass<<<MR, 512, pass_smem>>>(pairs);
    k_final<<<1, 256>>>(out, out_size);
}